// round 3
// baseline (speedup 1.0000x reference)
#include <cuda_runtime.h>

#define HDIM   256
#define MROWS  16      // batch rows per block
#define MPAD   20      // padded row stride (floats) to kill bank conflicts; 20*4=80B is 16B-aligned
#define TPB    256
#define LN_EPS 1e-5f

// ---- packed f32x2 helpers (sm_103a FFMA2 path; ptxas never emits this from C++) ----
__device__ __forceinline__ unsigned long long ffma2(unsigned long long a,
                                                    unsigned long long b,
                                                    unsigned long long c) {
    unsigned long long d;
    asm("fma.rn.f32x2 %0, %1, %2, %3;" : "=l"(d) : "l"(a), "l"(b), "l"(c));
    return d;
}
__device__ __forceinline__ unsigned long long pack2(float a, float b) {
    unsigned long long r;
    asm("mov.b64 %0, {%1, %2};" : "=l"(r) : "f"(a), "f"(b));
    return r;
}
__device__ __forceinline__ float2 unpack2(unsigned long long v) {
    float2 r;
    asm("mov.b64 {%0, %1}, %2;" : "=f"(r.x), "=f"(r.y) : "l"(v));
    return r;
}

// Accurate-enough fast tanh (~1e-6 rel err), immune to -use_fast_math tanhf->tanh.approx
// (tanh.approx's ~5e-4 error would compound over 512 steps).
__device__ __forceinline__ float tanh_fast(float v) {
    float e = __expf(2.0f * v);                 // inf for big v, 0 for very negative
    return 1.0f - __fdividef(2.0f, e + 1.0f);   // -> +1 / -1 at the limits, correct
}

__global__ void __launch_bounds__(TPB)
rnn_scan_kernel(const float* __restrict__ x,        // [B, T, 1]
                const float* __restrict__ W_embed,  // [1, H]
                const float* __restrict__ b_embed,  // [H]
                const float* __restrict__ W_up,     // [H, H] (in, out) row-major
                const float* __restrict__ b_up,     // [H]
                const float* __restrict__ gamma,    // [H]
                const float* __restrict__ beta,     // [H]
                const float* __restrict__ W_out,    // [H, 10]
                const float* __restrict__ b_out,    // [10]
                float* __restrict__ out,            // [B, 10]
                int B, int T)
{
    extern __shared__ unsigned char smem_raw[];
    float* tab  = (float*)smem_raw;            // [10][HDIM]      embed lookup (x in 0..9)
    float* s    = tab  + 10 * HDIM;            // [HDIM][MPAD]    s[k][m] = inp+h (k-major!)
    float* hbuf = s    + HDIM * MPAD;          // [HDIM][MPAD]    pre-LN tanh output, for reduction
    float* mu_s = hbuf + HDIM * MPAD;          // [MROWS]
    float* rs_s = mu_s + MROWS;                // [MROWS]
    unsigned char* xi = (unsigned char*)(rs_s + MROWS);  // [MROWS][T]

    const int tid = threadIdx.x;
    const int j   = tid;                       // this thread owns output column j
    const int b0  = blockIdx.x * MROWS;

    const float bu = b_up[j];
    const float g  = gamma[j];
    const float bt = beta[j];

    // ---- one-time: embed table (x is integer 0..9, so inp depends only on the digit) ----
    for (int idx = tid; idx < 10 * HDIM; idx += TPB) {
        int v  = idx / HDIM;
        int hh = idx - v * HDIM;
        tab[idx] = tanh_fast((float)v * W_embed[hh] + b_embed[hh]);
    }
    // ---- one-time: cache this block's x digits (coalesced over t) ----
    for (int idx = tid; idx < MROWS * T; idx += TPB) {
        int m = idx / T;
        int t = idx - m * T;
        xi[idx] = (unsigned char)__float2int_rn(x[(size_t)(b0 + m) * T + t]);
    }
    __syncthreads();

    // ---- init s for t=0 (h0 = 0 => s = inp only) ----
    {
        #pragma unroll
        for (int mq = 0; mq < MROWS; mq += 4) {
            float4 f;
            f.x = tab[(int)xi[(mq + 0) * T] * HDIM + j];
            f.y = tab[(int)xi[(mq + 1) * T] * HDIM + j];
            f.z = tab[(int)xi[(mq + 2) * T] * HDIM + j];
            f.w = tab[(int)xi[(mq + 3) * T] * HDIM + j];
            *(float4*)(s + j * MPAD + mq) = f;
        }
    }

    float hv[MROWS];

    for (int t = 0; t < T; t++) {
        __syncthreads();   // s for step t fully written

        // ---- GEMM: val[m] = sum_k s[k][m] * W_up[k][j], packed 2 rows per FFMA2 ----
        unsigned long long acc[MROWS / 2];
        #pragma unroll
        for (int p = 0; p < MROWS / 2; p++) acc[p] = 0ull;

        const float* Wc = W_up + j;            // column j, stride H (coalesced across threads)
        #pragma unroll 4
        for (int k = 0; k < HDIM; k++) {
            float w = __ldg(Wc + (size_t)k * HDIM);
            unsigned long long w2 = pack2(w, w);
            const ulonglong2* srow = (const ulonglong2*)(s + k * MPAD);  // broadcast reads
            ulonglong2 a0 = srow[0];
            ulonglong2 a1 = srow[1];
            ulonglong2 a2 = srow[2];
            ulonglong2 a3 = srow[3];
            acc[0] = ffma2(a0.x, w2, acc[0]);
            acc[1] = ffma2(a0.y, w2, acc[1]);
            acc[2] = ffma2(a1.x, w2, acc[2]);
            acc[3] = ffma2(a1.y, w2, acc[3]);
            acc[4] = ffma2(a2.x, w2, acc[4]);
            acc[5] = ffma2(a2.y, w2, acc[5]);
            acc[6] = ffma2(a3.x, w2, acc[6]);
            acc[7] = ffma2(a3.y, w2, acc[7]);
        }

        // ---- bias + tanh ----
        #pragma unroll
        for (int p = 0; p < MROWS / 2; p++) {
            float2 v = unpack2(acc[p]);
            hv[2 * p + 0] = tanh_fast(v.x + bu);
            hv[2 * p + 1] = tanh_fast(v.y + bu);
        }

        // ---- stash pre-LN values for the cross-column reduction (conflict-free STS.128) ----
        #pragma unroll
        for (int mq = 0; mq < MROWS; mq += 4) {
            float4 f = make_float4(hv[mq], hv[mq + 1], hv[mq + 2], hv[mq + 3]);
            *(float4*)(hbuf + j * MPAD + mq) = f;
        }
        __syncthreads();   // hbuf ready

        // ---- LayerNorm stats: 16 threads per row, 16 elements each, shfl tree ----
        {
            int m   = tid >> 4;
            int seg = tid & 15;
            float sum = 0.f, ss = 0.f;
            #pragma unroll
            for (int i = 0; i < 16; i++) {
                float v = hbuf[(i * 16 + seg) * MPAD + m];   // 2-way conflicts only
                sum += v;
                ss  += v * v;
            }
            #pragma unroll
            for (int o = 8; o >= 1; o >>= 1) {
                sum += __shfl_xor_sync(0xffffffffu, sum, o);
                ss  += __shfl_xor_sync(0xffffffffu, ss,  o);
            }
            if (seg == 0) {
                float mu  = sum * (1.0f / HDIM);
                float var = ss  * (1.0f / HDIM) - mu * mu;
                mu_s[m] = mu;
                rs_s[m] = rsqrtf(var + LN_EPS);
            }
        }
        __syncthreads();   // stats ready

        // ---- normalize (from registers) and build s for step t+1 (or final h) ----
        if (t + 1 < T) {
            #pragma unroll
            for (int mq = 0; mq < MROWS; mq += 4) {
                float4 f;
                f.x = (hv[mq + 0] - mu_s[mq + 0]) * rs_s[mq + 0] * g + bt
                      + tab[(int)xi[(mq + 0) * T + t + 1] * HDIM + j];
                f.y = (hv[mq + 1] - mu_s[mq + 1]) * rs_s[mq + 1] * g + bt
                      + tab[(int)xi[(mq + 1) * T + t + 1] * HDIM + j];
                f.z = (hv[mq + 2] - mu_s[mq + 2]) * rs_s[mq + 2] * g + bt
                      + tab[(int)xi[(mq + 2) * T + t + 1] * HDIM + j];
                f.w = (hv[mq + 3] - mu_s[mq + 3]) * rs_s[mq + 3] * g + bt
                      + tab[(int)xi[(mq + 3) * T + t + 1] * HDIM + j];
                *(float4*)(s + j * MPAD + mq) = f;
            }
        } else {
            #pragma unroll
            for (int mq = 0; mq < MROWS; mq += 4) {
                float4 f;
                f.x = (hv[mq + 0] - mu_s[mq + 0]) * rs_s[mq + 0] * g + bt;
                f.y = (hv[mq + 1] - mu_s[mq + 1]) * rs_s[mq + 1] * g + bt;
                f.z = (hv[mq + 2] - mu_s[mq + 2]) * rs_s[mq + 2] * g + bt;
                f.w = (hv[mq + 3] - mu_s[mq + 3]) * rs_s[mq + 3] * g + bt;
                *(float4*)(s + j * MPAD + mq) = f;   // s now holds final LN'd h
            }
        }
    }
    __syncthreads();

    // ---- output head: out[b0+m][c] = h_final[m] . W_out[:,c] + b_out[c]  (160 dots of 256) ----
    for (int o = tid; o < MROWS * 10; o += TPB) {
        int m = o / 10;
        int c = o - m * 10;
        float a = b_out[c];
        #pragma unroll 4
        for (int k = 0; k < HDIM; k++)
            a = fmaf(s[k * MPAD + m], __ldg(W_out + k * 10 + c), a);
        out[(size_t)(b0 + m) * 10 + c] = a;
    }
}

extern "C" void kernel_launch(void* const* d_in, const int* in_sizes, int n_in,
                              void* d_out, int out_size)
{
    const float* x       = (const float*)d_in[0];
    const float* W_embed = (const float*)d_in[1];
    const float* b_embed = (const float*)d_in[2];
    const float* W_up    = (const float*)d_in[3];
    const float* b_up    = (const float*)d_in[4];
    const float* gamma   = (const float*)d_in[5];
    const float* beta    = (const float*)d_in[6];
    const float* W_out   = (const float*)d_in[7];
    const float* b_out   = (const float*)d_in[8];
    float* out = (float*)d_out;

    int B = out_size / 10;          // 2048
    int T = in_sizes[0] / B;        // 512

    size_t smem = (size_t)(10 * HDIM + 2 * HDIM * MPAD + 2 * MROWS) * sizeof(float)
                + (size_t)MROWS * T + 64;
    cudaFuncSetAttribute(rnn_scan_kernel,
                         cudaFuncAttributeMaxDynamicSharedMemorySize, (int)smem);
    rnn_scan_kernel<<<B / MROWS, TPB, smem>>>(x, W_embed, b_embed, W_up, b_up,
                                              gamma, beta, W_out, b_out, out, B, T);
}

// round 4
// speedup vs baseline: 2.3519x; 2.3519x over previous
#include <cuda_runtime.h>

#define HDIM   256
#define MROWS  16      // batch rows per block
#define MPAD   20      // padded row stride for s (floats); 80B rows, 16B aligned
#define HPAD   260     // padded row stride for hbuf (floats); 1040B, 16B aligned
#define TPB    512
#define KTILE  32      // W k-rows per streamed tile (32KB)
#define NBUF   3       // triple-buffer -> one barrier per tile
#define LN_EPS 1e-5f

// ---- packed f32x2 (sm_103a FFMA2; ptxas never auto-emits from C++) ----
__device__ __forceinline__ unsigned long long ffma2(unsigned long long a,
                                                    unsigned long long b,
                                                    unsigned long long c) {
    unsigned long long d;
    asm("fma.rn.f32x2 %0, %1, %2, %3;" : "=l"(d) : "l"(a), "l"(b), "l"(c));
    return d;
}
__device__ __forceinline__ unsigned long long pack2(float a, float b) {
    unsigned long long r;
    asm("mov.b64 %0, {%1, %2};" : "=l"(r) : "f"(a), "f"(b));
    return r;
}
__device__ __forceinline__ float2 unpack2(unsigned long long v) {
    float2 r;
    asm("mov.b64 {%0, %1}, %2;" : "=f"(r.x), "=f"(r.y) : "l"(v));
    return r;
}

// Accurate fast tanh (~1e-6 rel err); recurrence is contractive so this holds to the end.
__device__ __forceinline__ float tanh_fast(float v) {
    float e = __expf(2.0f * v);
    return 1.0f - __fdividef(2.0f, e + 1.0f);
}

__device__ __forceinline__ unsigned smem_u32(const void* p) {
    unsigned r;
    asm("{ .reg .u64 t; cvta.to.shared.u64 t, %1; cvt.u32.u64 %0, t; }" : "=r"(r) : "l"(p));
    return r;
}
__device__ __forceinline__ void cp16(unsigned dst, const void* src) {
    asm volatile("cp.async.cg.shared.global [%0], [%1], 16;" :: "r"(dst), "l"(src));
}
__device__ __forceinline__ void cp_commit() { asm volatile("cp.async.commit_group;"); }
__device__ __forceinline__ void cp_wait1()  { asm volatile("cp.async.wait_group 1;" ::: "memory"); }
__device__ __forceinline__ void cp_wait0()  { asm volatile("cp.async.wait_group 0;" ::: "memory"); }

__global__ void __launch_bounds__(TPB, 1)
rnn_scan_kernel(const float* __restrict__ x,        // [B, T, 1]
                const float* __restrict__ W_embed,  // [1, H]
                const float* __restrict__ b_embed,  // [H]
                const float* __restrict__ W_up,     // [H, H] (in, out) row-major
                const float* __restrict__ b_up,     // [H]
                const float* __restrict__ gamma,    // [H]
                const float* __restrict__ beta,     // [H]
                const float* __restrict__ W_out,    // [H, 10]
                const float* __restrict__ b_out,    // [10]
                float* __restrict__ out,            // [B, 10]
                int B, int T)
{
    extern __shared__ unsigned char smem_raw[];
    float* Wt   = (float*)smem_raw;               // [NBUF][KTILE][HDIM]  streamed W tiles
    float* tab  = Wt   + NBUF * KTILE * HDIM;     // [10][HDIM]           embed lookup
    float* s    = tab  + 10 * HDIM;               // [HDIM][MPAD]         s[k][m] = inp + h
    float* hbuf = s    + HDIM * MPAD;             // [MROWS][HPAD]        pre-LN tanh, row-major
    float* mu_s = hbuf + MROWS * HPAD;            // [MROWS]
    float* rs_s = mu_s + MROWS;                   // [MROWS]
    unsigned char* xi = (unsigned char*)(rs_s + MROWS);   // [MROWS][T]

    const int tid  = threadIdx.x;
    const int j    = tid & (HDIM - 1);            // output column
    const int half = tid >> 8;                    // 0/1: which 8 rows
    const int m0   = half * 8;
    const int b0   = blockIdx.x * MROWS;
    const int NT   = 8 * T;                       // total W tiles streamed

    const float bu = b_up[j];
    const float gm = gamma[j];
    const float bt = beta[j];

    auto issue_tile = [&](int g) {
        int tile = g & 7;
        int buf  = g % 3;
        const char* src = (const char*)(W_up + tile * KTILE * HDIM);
        unsigned dstb = smem_u32(Wt + buf * KTILE * HDIM);
        #pragma unroll
        for (int r = 0; r < 4; r++)                        // 32KB / 512 thr = 64B = 4x16B
            cp16(dstb + (unsigned)(r * TPB + tid) * 16u, src + (size_t)(r * TPB + tid) * 16);
        cp_commit();
    };

    // ---- kick off the W pipeline immediately ----
    issue_tile(0);
    issue_tile(1);

    // ---- one-time: embed table (x is an integer digit 0..9) ----
    for (int idx = tid; idx < 10 * HDIM; idx += TPB) {
        int v  = idx / HDIM;
        int hh = idx - v * HDIM;
        tab[idx] = tanh_fast((float)v * W_embed[hh] + b_embed[hh]);
    }
    // ---- one-time: cache this block's digits ----
    for (int idx = tid; idx < MROWS * T; idx += TPB) {
        int m = idx / T;
        int t = idx - m * T;
        xi[idx] = (unsigned char)__float2int_rn(x[(size_t)(b0 + m) * T + t]);
    }
    __syncthreads();

    // ---- init s for t=0 (h0 = 0 => s = inp) ----
    {
        #pragma unroll
        for (int mq = 0; mq < 8; mq += 4) {
            float4 f;
            f.x = tab[(int)xi[(m0 + mq + 0) * T] * HDIM + j];
            f.y = tab[(int)xi[(m0 + mq + 1) * T] * HDIM + j];
            f.z = tab[(int)xi[(m0 + mq + 2) * T] * HDIM + j];
            f.w = tab[(int)xi[(m0 + mq + 3) * T] * HDIM + j];
            *(float4*)(s + j * MPAD + m0 + mq) = f;
        }
    }

    float hv[8];
    int g = 0;

    for (int t = 0; t < T; t++) {
        unsigned long long acc[4] = {0ull, 0ull, 0ull, 0ull};

        for (int tile = 0; tile < 8; tile++, g++) {
            if (g == NT - 1) cp_wait0(); else cp_wait1();   // tile g landed (this thread)
            __syncthreads();                                // all threads' pieces visible;
                                                            // also: s for step t ready (tile 0),
                                                            // buffer (g+2)%3 free for reuse
            if (g + 2 < NT) issue_tile(g + 2);

            const float* Wk = Wt + (g % 3) * KTILE * HDIM + j;
            const float* sk = s + (tile * KTILE) * MPAD + m0;
            #pragma unroll 8
            for (int kk = 0; kk < KTILE; kk++) {
                float w = Wk[kk * HDIM];                    // conflict-free LDS.32
                unsigned long long w2 = pack2(w, w);
                ulonglong2 a0 = *(const ulonglong2*)(sk + kk * MPAD);      // broadcast
                ulonglong2 a1 = *(const ulonglong2*)(sk + kk * MPAD + 4);  // broadcast
                acc[0] = ffma2(a0.x, w2, acc[0]);
                acc[1] = ffma2(a0.y, w2, acc[1]);
                acc[2] = ffma2(a1.x, w2, acc[2]);
                acc[3] = ffma2(a1.y, w2, acc[3]);
            }
        }

        // ---- bias + tanh ----
        #pragma unroll
        for (int p = 0; p < 4; p++) {
            float2 v = unpack2(acc[p]);
            hv[2 * p + 0] = tanh_fast(v.x + bu);
            hv[2 * p + 1] = tanh_fast(v.y + bu);
        }

        // ---- stash pre-LN values, row-major (conflict-free STS.32 per row) ----
        #pragma unroll
        for (int i = 0; i < 8; i++)
            hbuf[(m0 + i) * HPAD + j] = hv[i];
        __syncthreads();

        // ---- LN stats: one warp per row, float4 reads, full-warp shfl tree ----
        {
            int w = tid >> 5;                               // 16 warps == 16 rows
            int l = tid & 31;
            const float4* row = (const float4*)(hbuf + w * HPAD);
            float4 v0 = row[l * 2 + 0];
            float4 v1 = row[l * 2 + 1];
            float sum = v0.x + v0.y + v0.z + v0.w + v1.x + v1.y + v1.z + v1.w;
            float ss  = v0.x * v0.x + v0.y * v0.y + v0.z * v0.z + v0.w * v0.w
                      + v1.x * v1.x + v1.y * v1.y + v1.z * v1.z + v1.w * v1.w;
            #pragma unroll
            for (int o = 16; o >= 1; o >>= 1) {
                sum += __shfl_xor_sync(0xffffffffu, sum, o);
                ss  += __shfl_xor_sync(0xffffffffu, ss,  o);
            }
            if (l == 0) {
                float mu  = sum * (1.0f / HDIM);
                float var = ss  * (1.0f / HDIM) - mu * mu;
                mu_s[w] = mu;
                rs_s[w] = rsqrtf(var + LN_EPS);
            }
        }
        __syncthreads();

        // ---- normalize from registers; build s for step t+1 (or final h) ----
        if (t + 1 < T) {
            #pragma unroll
            for (int mq = 0; mq < 8; mq += 4) {
                float4 f;
                f.x = (hv[mq + 0] - mu_s[m0 + mq + 0]) * rs_s[m0 + mq + 0] * gm + bt
                      + tab[(int)xi[(m0 + mq + 0) * T + t + 1] * HDIM + j];
                f.y = (hv[mq + 1] - mu_s[m0 + mq + 1]) * rs_s[m0 + mq + 1] * gm + bt
                      + tab[(int)xi[(m0 + mq + 1) * T + t + 1] * HDIM + j];
                f.z = (hv[mq + 2] - mu_s[m0 + mq + 2]) * rs_s[m0 + mq + 2] * gm + bt
                      + tab[(int)xi[(m0 + mq + 2) * T + t + 1] * HDIM + j];
                f.w = (hv[mq + 3] - mu_s[m0 + mq + 3]) * rs_s[m0 + mq + 3] * gm + bt
                      + tab[(int)xi[(m0 + mq + 3) * T + t + 1] * HDIM + j];
                *(float4*)(s + j * MPAD + m0 + mq) = f;
            }
        } else {
            #pragma unroll
            for (int mq = 0; mq < 8; mq += 4) {
                float4 f;
                f.x = (hv[mq + 0] - mu_s[m0 + mq + 0]) * rs_s[m0 + mq + 0] * gm + bt;
                f.y = (hv[mq + 1] - mu_s[m0 + mq + 1]) * rs_s[m0 + mq + 1] * gm + bt;
                f.z = (hv[mq + 2] - mu_s[m0 + mq + 2]) * rs_s[m0 + mq + 2] * gm + bt;
                f.w = (hv[mq + 3] - mu_s[m0 + mq + 3]) * rs_s[m0 + mq + 3] * gm + bt;
                *(float4*)(s + j * MPAD + m0 + mq) = f;     // s now holds final LN'd h
            }
        }
    }
    __syncthreads();

    // ---- output head: out[b0+m][c] = h_final[m] . W_out[:,c] + b_out[c] ----
    for (int o = tid; o < MROWS * 10; o += TPB) {
        int m = o / 10;
        int c = o - m * 10;
        float a = b_out[c];
        #pragma unroll 8
        for (int k = 0; k < HDIM; k++)
            a = fmaf(s[k * MPAD + m], __ldg(W_out + k * 10 + c), a);
        out[(size_t)(b0 + m) * 10 + c] = a;
    }
}

extern "C" void kernel_launch(void* const* d_in, const int* in_sizes, int n_in,
                              void* d_out, int out_size)
{
    const float* x       = (const float*)d_in[0];
    const float* W_embed = (const float*)d_in[1];
    const float* b_embed = (const float*)d_in[2];
    const float* W_up    = (const float*)d_in[3];
    const float* b_up    = (const float*)d_in[4];
    const float* gamma   = (const float*)d_in[5];
    const float* beta    = (const float*)d_in[6];
    const float* W_out   = (const float*)d_in[7];
    const float* b_out   = (const float*)d_in[8];
    float* out = (float*)d_out;

    int B = out_size / 10;          // 2048
    int T = in_sizes[0] / B;        // 512

    size_t smem = (size_t)(NBUF * KTILE * HDIM      // W tiles      (98304 B)
                         + 10 * HDIM                // tab          (10240 B)
                         + HDIM * MPAD              // s            (20480 B)
                         + MROWS * HPAD             // hbuf         (16640 B)
                         + 2 * MROWS) * sizeof(float)
                + (size_t)MROWS * T                  // xi           (8192 B)
                + 64;
    cudaFuncSetAttribute(rnn_scan_kernel,
                         cudaFuncAttributeMaxDynamicSharedMemorySize, (int)smem);
    rnn_scan_kernel<<<B / MROWS, TPB, smem>>>(x, W_embed, b_embed, W_up, b_up,
                                              gamma, beta, W_out, b_out, out, B, T);
}

// round 5
// speedup vs baseline: 2.5911x; 1.1017x over previous
#include <cuda_runtime.h>

#define HDIM   256
#define HR     8                      // rows per half-pipeline
#define TPB    512
#define KTILE  32                     // k-rows per W tile
#define KBYTES (KTILE * HDIM * 4)     // 32768
#define NBUF   4
#define SPAD   12                     // s row stride (floats), 48B, 16B-aligned
#define HPAD   260                    // hbuf row stride (floats), 1040B
#define LN_EPS 1e-5f

// ---- packed f32x2 (sm_103a FFMA2; ptxas never auto-emits from C++) ----
__device__ __forceinline__ unsigned long long ffma2(unsigned long long a,
                                                    unsigned long long b,
                                                    unsigned long long c) {
    unsigned long long d;
    asm("fma.rn.f32x2 %0, %1, %2, %3;" : "=l"(d) : "l"(a), "l"(b), "l"(c));
    return d;
}
__device__ __forceinline__ unsigned long long pack2(float a, float b) {
    unsigned long long r;
    asm("mov.b64 %0, {%1, %2};" : "=l"(r) : "f"(a), "f"(b));
    return r;
}
__device__ __forceinline__ float2 unpack2(unsigned long long v) {
    float2 r;
    asm("mov.b64 {%0, %1}, %2;" : "=f"(r.x), "=f"(r.y) : "l"(v));
    return r;
}

// Accurate fast tanh (~1e-6 rel err); recurrence is contractive (verified: no compounding).
__device__ __forceinline__ float tanh_fast(float v) {
    float e = __expf(2.0f * v);
    return 1.0f - __fdividef(2.0f, e + 1.0f);
}

__device__ __forceinline__ unsigned smem_u32(const void* p) {
    unsigned r;
    asm("{ .reg .u64 t; cvta.to.shared.u64 t, %1; cvt.u32.u64 %0, t; }" : "=r"(r) : "l"(p));
    return r;
}

// ---- mbarrier + bulk-copy primitives ----
__device__ __forceinline__ void mb_init(unsigned addr, unsigned cnt) {
    asm volatile("mbarrier.init.shared.b64 [%0], %1;" :: "r"(addr), "r"(cnt) : "memory");
}
__device__ __forceinline__ void mb_expect_tx(unsigned addr, unsigned bytes) {
    asm volatile("mbarrier.arrive.expect_tx.shared.b64 _, [%0], %1;"
                 :: "r"(addr), "r"(bytes) : "memory");
}
__device__ __forceinline__ void mb_arrive(unsigned addr) {
    asm volatile("mbarrier.arrive.shared.b64 _, [%0];" :: "r"(addr) : "memory");
}
__device__ __forceinline__ void mb_wait(unsigned addr, int parity) {
    asm volatile(
        "{\n\t.reg .pred P;\n"
        "W%=:\n\t"
        "mbarrier.try_wait.parity.acquire.cta.shared::cta.b64 P, [%0], %1, 0x989680;\n\t"
        "@!P bra W%=;\n\t}"
        :: "r"(addr), "r"(parity) : "memory");
}
__device__ __forceinline__ void bulk_cp(unsigned dst, const void* src, unsigned bytes,
                                        unsigned mbar) {
    asm volatile("cp.async.bulk.shared::cluster.global.mbarrier::complete_tx::bytes "
                 "[%0], [%1], %2, [%3];"
                 :: "r"(dst), "l"(src), "r"(bytes), "r"(mbar) : "memory");
}
__device__ __forceinline__ void nbar_sync(int id, int cnt) {
    asm volatile("bar.sync %0, %1;" :: "r"(id), "r"(cnt) : "memory");
}

__global__ void __launch_bounds__(TPB, 1)
rnn_scan_kernel(const float* __restrict__ x,        // [B, T, 1]
                const float* __restrict__ W_embed,  // [1, H]
                const float* __restrict__ b_embed,  // [H]
                const float* __restrict__ W_up,     // [H, H] (in, out) row-major
                const float* __restrict__ b_up,     // [H]
                const float* __restrict__ gamma,    // [H]
                const float* __restrict__ beta,     // [H]
                const float* __restrict__ W_out,    // [H, 10]
                const float* __restrict__ b_out,    // [10]
                float* __restrict__ out,            // [B, 10]
                int B, int T)
{
    extern __shared__ unsigned char smem_raw[];
    float* Wt    = (float*)smem_raw;                  // [NBUF][KTILE][HDIM]   131072 B
    float* tab   = Wt    + NBUF * KTILE * HDIM;       // [10][HDIM]             10240 B
    float* sAll  = tab   + 10 * HDIM;                 // [2][HDIM][SPAD]        24576 B
    float* hAll  = sAll  + 2 * HDIM * SPAD;           // [2][HR][HPAD]          16640 B
    float* stats = hAll  + 2 * HR * HPAD;             // [2][16] (mu|rs)          128 B
    unsigned char* xi = (unsigned char*)(stats + 32); // [16][T]                 8192 B

    __shared__ unsigned long long mbar[2 * NBUF];     // full[0..3], empty[0..3]

    const int tid  = threadIdx.x;
    const int half = tid >> 8;                        // 0 / 1: independent pipeline
    const int ht   = tid & 255;
    const int j    = ht;                              // output column
    const int hb   = 1 + half;                        // named barrier id per half
    const int b0   = blockIdx.x * 16;
    const int m0g  = half * HR;                       // first row (within block) of this half
    const int NT   = 8 * T;                           // total W tiles consumed

    float* sH  = sAll + half * HDIM * SPAD;           // [HDIM][SPAD]  s[k][m] for this half
    float* hbH = hAll + half * HR * HPAD;             // [HR][HPAD]
    float* muH = stats + half * 16;
    float* rsH = muH + 8;

    const unsigned mb0   = smem_u32(mbar);
    const unsigned WtA   = smem_u32(Wt);
    auto full_a  = [&](int i) -> unsigned { return mb0 + (unsigned)i * 8u; };
    auto empty_a = [&](int i) -> unsigned { return mb0 + 32u + (unsigned)i * 8u; };

    const float bu = b_up[j];
    const float gm = gamma[j];
    const float bt = beta[j];

    // ---- init mbarriers (full: tx-based count 1; empty: one arrive per half) ----
    if (tid == 0) {
        #pragma unroll
        for (int i = 0; i < NBUF; i++) { mb_init(full_a(i), 1); mb_init(empty_a(i), 2); }
    }

    // ---- one-time: embed table (x is an integer digit 0..9) ----
    for (int idx = tid; idx < 10 * HDIM; idx += TPB) {
        int v  = idx / HDIM;
        int hh = idx - v * HDIM;
        tab[idx] = tanh_fast((float)v * W_embed[hh] + b_embed[hh]);
    }
    // ---- one-time: cache this block's digits ----
    for (int idx = tid; idx < 16 * T; idx += TPB) {
        int m = idx / T;
        int t = idx - m * T;
        xi[idx] = (unsigned char)__float2int_rn(x[(size_t)(b0 + m) * T + t]);
    }
    __syncthreads();                                   // mbarriers + tab + xi visible

    // producer: issue tile p into buffer p%4 (blocking on buffer-empty)
    auto issue = [&](int p) {
        int buf = p & 3;
        mb_wait(empty_a(buf), ((p >> 2) & 1) ^ 1);     // fresh barriers pass (parity trick)
        mb_expect_tx(full_a(buf), KBYTES);
        bulk_cp(WtA + (unsigned)buf * KBYTES,
                W_up + (size_t)(p & 7) * KTILE * HDIM, KBYTES, full_a(buf));
    };
    if (tid == 0) { issue(0); issue(1); issue(2); }

    // ---- init s for t=0 (h0 = 0 => s = inp) ----
    {
        float2 v01, v23, v45, v67;
        v01.x = tab[(int)xi[(m0g + 0) * T] * HDIM + j];
        v01.y = tab[(int)xi[(m0g + 1) * T] * HDIM + j];
        v23.x = tab[(int)xi[(m0g + 2) * T] * HDIM + j];
        v23.y = tab[(int)xi[(m0g + 3) * T] * HDIM + j];
        v45.x = tab[(int)xi[(m0g + 4) * T] * HDIM + j];
        v45.y = tab[(int)xi[(m0g + 5) * T] * HDIM + j];
        v67.x = tab[(int)xi[(m0g + 6) * T] * HDIM + j];
        v67.y = tab[(int)xi[(m0g + 7) * T] * HDIM + j];
        *(float4*)(sH + j * SPAD)     = make_float4(v01.x, v01.y, v23.x, v23.y);
        *(float4*)(sH + j * SPAD + 4) = make_float4(v45.x, v45.y, v67.x, v67.y);
    }
    nbar_sync(hb, 256);                                // s ready for this half

    float hv[8];
    int g = half ? 0 : 0;  // both halves consume tiles 0..NT-1 at their own pace
    g = 0;

    for (int t = 0; t < T; t++) {
        unsigned long long acc[4] = {0ull, 0ull, 0ull, 0ull};

        for (int tile = 0; tile < 8; tile++, g++) {
            if (tid == 0 && g + 3 < NT) issue(g + 3);  // keep pipe 3 deep
            mb_wait(full_a(g & 3), (g >> 2) & 1);      // tile data landed

            const float* Wk = Wt + (g & 3) * KTILE * HDIM + j;
            const float* sk = sH + (tile * KTILE) * SPAD;
            #pragma unroll 8
            for (int kk = 0; kk < KTILE; kk++) {
                float w = Wk[kk * HDIM];               // conflict-free LDS.32
                unsigned long long w2 = pack2(w, w);
                ulonglong2 a0 = *(const ulonglong2*)(sk + kk * SPAD);      // bcast 16B
                ulonglong2 a1 = *(const ulonglong2*)(sk + kk * SPAD + 4);  // bcast 16B
                acc[0] = ffma2(a0.x, w2, acc[0]);
                acc[1] = ffma2(a0.y, w2, acc[1]);
                acc[2] = ffma2(a1.x, w2, acc[2]);
                acc[3] = ffma2(a1.y, w2, acc[3]);
            }
            nbar_sync(hb, 256);                        // this half done reading buffer
            if (ht == 0) mb_arrive(empty_a(g & 3));    // release buffer (1 of 2 arrivals)
        }

        // ---- bias + tanh ----
        #pragma unroll
        for (int p = 0; p < 4; p++) {
            float2 v = unpack2(acc[p]);
            hv[2 * p + 0] = tanh_fast(v.x + bu);
            hv[2 * p + 1] = tanh_fast(v.y + bu);
        }

        // ---- stash pre-LN values, row-major (conflict-free STS.32) ----
        #pragma unroll
        for (int i = 0; i < 8; i++)
            hbH[i * HPAD + j] = hv[i];
        nbar_sync(hb, 256);

        // ---- LN stats: warp w of this half handles row w; float4 + shfl tree ----
        {
            int w = ht >> 5;                           // 8 warps == 8 rows
            int l = ht & 31;
            const float4* row = (const float4*)(hbH + w * HPAD);
            float4 v0 = row[l * 2 + 0];
            float4 v1 = row[l * 2 + 1];
            float sum = v0.x + v0.y + v0.z + v0.w + v1.x + v1.y + v1.z + v1.w;
            float ss  = v0.x * v0.x + v0.y * v0.y + v0.z * v0.z + v0.w * v0.w
                      + v1.x * v1.x + v1.y * v1.y + v1.z * v1.z + v1.w * v1.w;
            #pragma unroll
            for (int o = 16; o >= 1; o >>= 1) {
                sum += __shfl_xor_sync(0xffffffffu, sum, o);
                ss  += __shfl_xor_sync(0xffffffffu, ss,  o);
            }
            if (l == 0) {
                float mu  = sum * (1.0f / HDIM);
                float var = ss  * (1.0f / HDIM) - mu * mu;
                muH[w] = mu;
                rsH[w] = rsqrtf(var + LN_EPS);
            }
        }
        nbar_sync(hb, 256);

        // ---- normalize from registers; build s for step t+1 (or final h) ----
        if (t + 1 < T) {
            float4 f0, f1;
            f0.x = (hv[0] - muH[0]) * rsH[0] * gm + bt + tab[(int)xi[(m0g + 0) * T + t + 1] * HDIM + j];
            f0.y = (hv[1] - muH[1]) * rsH[1] * gm + bt + tab[(int)xi[(m0g + 1) * T + t + 1] * HDIM + j];
            f0.z = (hv[2] - muH[2]) * rsH[2] * gm + bt + tab[(int)xi[(m0g + 2) * T + t + 1] * HDIM + j];
            f0.w = (hv[3] - muH[3]) * rsH[3] * gm + bt + tab[(int)xi[(m0g + 3) * T + t + 1] * HDIM + j];
            f1.x = (hv[4] - muH[4]) * rsH[4] * gm + bt + tab[(int)xi[(m0g + 4) * T + t + 1] * HDIM + j];
            f1.y = (hv[5] - muH[5]) * rsH[5] * gm + bt + tab[(int)xi[(m0g + 5) * T + t + 1] * HDIM + j];
            f1.z = (hv[6] - muH[6]) * rsH[6] * gm + bt + tab[(int)xi[(m0g + 6) * T + t + 1] * HDIM + j];
            f1.w = (hv[7] - muH[7]) * rsH[7] * gm + bt + tab[(int)xi[(m0g + 7) * T + t + 1] * HDIM + j];
            *(float4*)(sH + j * SPAD)     = f0;
            *(float4*)(sH + j * SPAD + 4) = f1;
        } else {
            float4 f0, f1;
            f0.x = (hv[0] - muH[0]) * rsH[0] * gm + bt;
            f0.y = (hv[1] - muH[1]) * rsH[1] * gm + bt;
            f0.z = (hv[2] - muH[2]) * rsH[2] * gm + bt;
            f0.w = (hv[3] - muH[3]) * rsH[3] * gm + bt;
            f1.x = (hv[4] - muH[4]) * rsH[4] * gm + bt;
            f1.y = (hv[5] - muH[5]) * rsH[5] * gm + bt;
            f1.z = (hv[6] - muH[6]) * rsH[6] * gm + bt;
            f1.w = (hv[7] - muH[7]) * rsH[7] * gm + bt;
            *(float4*)(sH + j * SPAD)     = f0;        // s now holds final LN'd h
            *(float4*)(sH + j * SPAD + 4) = f1;
        }
        nbar_sync(hb, 256);                            // s' visible before next step
    }

    // ---- output head: out[b0+m0g+m][c] = h_final[m] . W_out[:,c] + b_out[c] ----
    if (ht < HR * 10) {
        int m = ht / 10;
        int c = ht - m * 10;
        float a = b_out[c];
        #pragma unroll 8
        for (int k = 0; k < HDIM; k++)
            a = fmaf(sH[k * SPAD + m], __ldg(W_out + k * 10 + c), a);
        out[(size_t)(b0 + m0g + m) * 10 + c] = a;
    }
}

extern "C" void kernel_launch(void* const* d_in, const int* in_sizes, int n_in,
                              void* d_out, int out_size)
{
    const float* x       = (const float*)d_in[0];
    const float* W_embed = (const float*)d_in[1];
    const float* b_embed = (const float*)d_in[2];
    const float* W_up    = (const float*)d_in[3];
    const float* b_up    = (const float*)d_in[4];
    const float* gamma   = (const float*)d_in[5];
    const float* beta    = (const float*)d_in[6];
    const float* W_out   = (const float*)d_in[7];
    const float* b_out   = (const float*)d_in[8];
    float* out = (float*)d_out;

    int B = out_size / 10;          // 2048
    int T = in_sizes[0] / B;        // 512

    size_t smem = (size_t)NBUF * KTILE * HDIM * 4     // W buffers   131072
                + (size_t)10 * HDIM * 4               // tab          10240
                + (size_t)2 * HDIM * SPAD * 4         // s            24576
                + (size_t)2 * HR * HPAD * 4           // hbuf         16640
                + 32 * 4                              // stats
                + (size_t)16 * T                      // xi            8192
                + 64;
    cudaFuncSetAttribute(rnn_scan_kernel,
                         cudaFuncAttributeMaxDynamicSharedMemorySize, (int)smem);
    rnn_scan_kernel<<<B / 16, TPB, smem>>>(x, W_embed, b_embed, W_up, b_up,
                                           gamma, beta, W_out, b_out, out, B, T);
}

// round 6
// speedup vs baseline: 3.0088x; 1.1612x over previous
#include <cuda_runtime.h>

#define HDIM   256
#define HR     8                      // rows per half-pipeline
#define TPB    512
#define KTILE  32                     // k-rows per W tile
#define KBYTES (KTILE * HDIM * 4)     // 32768
#define NBUF   4
#define SPAD   12                     // s row stride (floats), 48B
#define HPAD   260                    // hbuf row stride (floats)
#define LN_EPS 1e-5f

// ---- packed f32x2 ----
__device__ __forceinline__ unsigned long long ffma2(unsigned long long a,
                                                    unsigned long long b,
                                                    unsigned long long c) {
    unsigned long long d;
    asm("fma.rn.f32x2 %0, %1, %2, %3;" : "=l"(d) : "l"(a), "l"(b), "l"(c));
    return d;
}
__device__ __forceinline__ unsigned long long addf32x2(unsigned long long a,
                                                       unsigned long long b) {
    unsigned long long d;
    asm("add.rn.f32x2 %0, %1, %2;" : "=l"(d) : "l"(a), "l"(b));
    return d;
}
__device__ __forceinline__ unsigned long long pack2(float a, float b) {
    unsigned long long r;
    asm("mov.b64 %0, {%1, %2};" : "=l"(r) : "f"(a), "f"(b));
    return r;
}
__device__ __forceinline__ float2 unpack2(unsigned long long v) {
    float2 r;
    asm("mov.b64 {%0, %1}, %2;" : "=f"(r.x), "=f"(r.y) : "l"(v));
    return r;
}

// Accurate fast tanh (~1e-6 rel err); recurrence is contractive (verified).
__device__ __forceinline__ float tanh_fast(float v) {
    float e = __expf(2.0f * v);
    return 1.0f - __fdividef(2.0f, e + 1.0f);
}

__device__ __forceinline__ unsigned smem_u32(const void* p) {
    unsigned r;
    asm("{ .reg .u64 t; cvta.to.shared.u64 t, %1; cvt.u32.u64 %0, t; }" : "=r"(r) : "l"(p));
    return r;
}

// ---- mbarrier + bulk-copy primitives ----
__device__ __forceinline__ void mb_init(unsigned addr, unsigned cnt) {
    asm volatile("mbarrier.init.shared.b64 [%0], %1;" :: "r"(addr), "r"(cnt) : "memory");
}
__device__ __forceinline__ void mb_expect_tx(unsigned addr, unsigned bytes) {
    asm volatile("mbarrier.arrive.expect_tx.shared.b64 _, [%0], %1;"
                 :: "r"(addr), "r"(bytes) : "memory");
}
__device__ __forceinline__ void mb_arrive(unsigned addr) {
    asm volatile("mbarrier.arrive.shared.b64 _, [%0];" :: "r"(addr) : "memory");
}
__device__ __forceinline__ void mb_wait(unsigned addr, int parity) {
    asm volatile(
        "{\n\t.reg .pred P;\n"
        "W%=:\n\t"
        "mbarrier.try_wait.parity.acquire.cta.shared::cta.b64 P, [%0], %1, 0x989680;\n\t"
        "@!P bra W%=;\n\t}"
        :: "r"(addr), "r"(parity) : "memory");
}
__device__ __forceinline__ void bulk_cp(unsigned dst, const void* src, unsigned bytes,
                                        unsigned mbar) {
    asm volatile("cp.async.bulk.shared::cluster.global.mbarrier::complete_tx::bytes "
                 "[%0], [%1], %2, [%3];"
                 :: "r"(dst), "l"(src), "r"(bytes), "r"(mbar) : "memory");
}
__device__ __forceinline__ void nbar_sync(int id, int cnt) {
    asm volatile("bar.sync %0, %1;" :: "r"(id), "r"(cnt) : "memory");
}

__global__ void __launch_bounds__(TPB, 1)
rnn_scan_kernel(const float* __restrict__ x,        // [B, T, 1]
                const float* __restrict__ W_embed,  // [1, H]
                const float* __restrict__ b_embed,  // [H]
                const float* __restrict__ W_up,     // [H, H]
                const float* __restrict__ b_up,     // [H]
                const float* __restrict__ gamma,    // [H]
                const float* __restrict__ beta,     // [H]
                const float* __restrict__ W_out,    // [H, 10]
                const float* __restrict__ b_out,    // [10]
                float* __restrict__ out,            // [B, 10]
                int B, int T)
{
    extern __shared__ unsigned char smem_raw[];
    float* Wt    = (float*)smem_raw;                     // [NBUF][KTILE][HDIM] 131072 B
    float* tab   = Wt    + NBUF * KTILE * HDIM;          // [10][HDIM]           10240 B
    float* sAll  = tab   + 10 * HDIM;                    // [2][HDIM][SPAD]      24576 B
    float* hAll  = sAll  + 2 * HDIM * SPAD;              // [2][HR][HPAD]        16640 B
    unsigned long long* partAll =
        (unsigned long long*)(hAll + 2 * HR * HPAD);     // [2][8][128] ull      16384 B
    float* stats = (float*)(partAll + 2 * 8 * 128);      // [2][16]                128 B
    unsigned char* xi = (unsigned char*)(stats + 32);    // [16][T]               8192 B

    __shared__ unsigned long long mbar[2 * NBUF];        // full[0..3], empty[0..3]

    const int tid   = threadIdx.x;
    const int half  = tid >> 8;                          // independent pipeline
    const int ht    = tid & 255;
    const int group = ht >> 7;                           // k-split group 0/1
    const int slot  = ht & 127;
    const int j0    = slot * 2;                          // this thread's 2 columns
    const int hb    = 1 + half;                          // half barrier (256)
    const int gb    = 3 + half * 2 + group;              // group barrier (128)
    const int b0    = blockIdx.x * 16;
    const int m0g   = half * HR;
    const int NT    = 8 * T;

    float* sH  = sAll  + half * HDIM * SPAD;
    float* hbH = hAll  + half * HR * HPAD;
    unsigned long long* partH = partAll + half * 8 * 128;
    float* muH = stats + half * 16;
    float* rsH = muH + 8;

    const unsigned mb0 = smem_u32(mbar);
    const unsigned WtA = smem_u32(Wt);
    auto full_a  = [&](int i) -> unsigned { return mb0 + (unsigned)i * 8u; };
    auto empty_a = [&](int i) -> unsigned { return mb0 + 32u + (unsigned)i * 8u; };

    const float2 bu = *(const float2*)(b_up  + j0);
    const float2 gm = *(const float2*)(gamma + j0);
    const float2 bt = *(const float2*)(beta  + j0);

    if (tid == 0) {
        #pragma unroll
        for (int i = 0; i < NBUF; i++) { mb_init(full_a(i), 1); mb_init(empty_a(i), 2); }
    }

    // ---- one-time: embed table (x is an integer digit 0..9) ----
    for (int idx = tid; idx < 10 * HDIM; idx += TPB) {
        int v  = idx / HDIM;
        int hh = idx - v * HDIM;
        tab[idx] = tanh_fast((float)v * W_embed[hh] + b_embed[hh]);
    }
    for (int idx = tid; idx < 16 * T; idx += TPB) {
        int m = idx / T;
        int t = idx - m * T;
        xi[idx] = (unsigned char)__float2int_rn(x[(size_t)(b0 + m) * T + t]);
    }
    __syncthreads();

    auto issue = [&](int p) {
        int buf = p & 3;
        mb_wait(empty_a(buf), ((p >> 2) & 1) ^ 1);
        mb_expect_tx(full_a(buf), KBYTES);
        bulk_cp(WtA + (unsigned)buf * KBYTES,
                W_up + (size_t)(p & 7) * KTILE * HDIM, KBYTES, full_a(buf));
    };
    // two producers (both in half 0): tid 0 pre-issues even base, tid 128 odd
    if (tid == 0)   { issue(0); issue(2); }
    if (tid == 128) { issue(1); }

    // ---- init s for t=0 (h0=0 => s = inp); group 0 builds its 2 columns ----
    if (group == 0) {
        float nv0[8], nv1[8];
        #pragma unroll
        for (int i = 0; i < 8; i++) {
            int d = (int)xi[(m0g + i) * T];
            float2 tv = *(const float2*)(tab + d * HDIM + j0);
            nv0[i] = tv.x; nv1[i] = tv.y;
        }
        *(float4*)(sH + j0 * SPAD)           = make_float4(nv0[0], nv0[1], nv0[2], nv0[3]);
        *(float4*)(sH + j0 * SPAD + 4)       = make_float4(nv0[4], nv0[5], nv0[6], nv0[7]);
        *(float4*)(sH + (j0 + 1) * SPAD)     = make_float4(nv1[0], nv1[1], nv1[2], nv1[3]);
        *(float4*)(sH + (j0 + 1) * SPAD + 4) = make_float4(nv1[4], nv1[5], nv1[6], nv1[7]);
    }
    nbar_sync(hb, 256);

    const bool producer = (tid == 0) || (tid == 128);
    float hv[2][8];

    for (int t = 0; t < T; t++) {
        unsigned long long acc[2][4];
        #pragma unroll
        for (int c = 0; c < 2; c++)
            #pragma unroll
            for (int p = 0; p < 4; p++) acc[c][p] = 0ull;

        // ---- k-loop: this group's 4 interleaved tiles (128 k-rows) ----
        #pragma unroll 1
        for (int it = 0; it < 4; it++) {
            const int lt = it * 2 + group;               // local tile 0..7
            const int G  = t * 8 + lt;                   // global tile
            if (producer && G + 3 < NT) issue(G + 3);    // evens issue odds & vice versa
            mb_wait(full_a(G & 3), (G >> 2) & 1);

            const float* Wk = Wt + (G & 3) * (KTILE * HDIM) + j0;
            const float* sk = sH + (lt * KTILE) * SPAD;
            #pragma unroll 8
            for (int kk = 0; kk < KTILE; kk++) {
                float2 w = *(const float2*)(Wk + kk * HDIM);     // LDS.64, coalesced
                unsigned long long w20 = pack2(w.x, w.x);
                unsigned long long w21 = pack2(w.y, w.y);
                ulonglong2 a0 = *(const ulonglong2*)(sk + kk * SPAD);      // bcast
                ulonglong2 a1 = *(const ulonglong2*)(sk + kk * SPAD + 4);  // bcast
                acc[0][0] = ffma2(a0.x, w20, acc[0][0]);
                acc[0][1] = ffma2(a0.y, w20, acc[0][1]);
                acc[0][2] = ffma2(a1.x, w20, acc[0][2]);
                acc[0][3] = ffma2(a1.y, w20, acc[0][3]);
                acc[1][0] = ffma2(a0.x, w21, acc[1][0]);
                acc[1][1] = ffma2(a0.y, w21, acc[1][1]);
                acc[1][2] = ffma2(a1.x, w21, acc[1][2]);
                acc[1][3] = ffma2(a1.y, w21, acc[1][3]);
            }
            nbar_sync(gb, 128);                          // group done with buffer
            if (slot == 0) mb_arrive(empty_a(G & 3));    // 1 of 2 arrivals
        }

        // ---- k-reduction: group 1 -> smem, group 0 adds ----
        if (group == 1) {
            #pragma unroll
            for (int c = 0; c < 2; c++)
                #pragma unroll
                for (int p = 0; p < 4; p++)
                    partH[(c * 4 + p) * 128 + slot] = acc[c][p];
        }
        nbar_sync(hb, 256);

        if (group == 0) {
            #pragma unroll
            for (int c = 0; c < 2; c++) {
                float bc = (c == 0) ? bu.x : bu.y;
                #pragma unroll
                for (int p = 0; p < 4; p++) {
                    acc[c][p] = addf32x2(acc[c][p], partH[(c * 4 + p) * 128 + slot]);
                    float2 v = unpack2(acc[c][p]);
                    hv[c][2 * p + 0] = tanh_fast(v.x + bc);
                    hv[c][2 * p + 1] = tanh_fast(v.y + bc);
                }
            }
            #pragma unroll
            for (int i = 0; i < 8; i++) {
                hbH[i * HPAD + j0]     = hv[0][i];
                hbH[i * HPAD + j0 + 1] = hv[1][i];
            }
        }
        nbar_sync(hb, 256);

        // ---- LN stats: 8 warps of this half, one per row ----
        {
            int w = ht >> 5;
            int l = ht & 31;
            const float4* row = (const float4*)(hbH + w * HPAD);
            float4 v0 = row[l * 2 + 0];
            float4 v1 = row[l * 2 + 1];
            float sum = v0.x + v0.y + v0.z + v0.w + v1.x + v1.y + v1.z + v1.w;
            float ss  = v0.x * v0.x + v0.y * v0.y + v0.z * v0.z + v0.w * v0.w
                      + v1.x * v1.x + v1.y * v1.y + v1.z * v1.z + v1.w * v1.w;
            #pragma unroll
            for (int o = 16; o >= 1; o >>= 1) {
                sum += __shfl_xor_sync(0xffffffffu, sum, o);
                ss  += __shfl_xor_sync(0xffffffffu, ss,  o);
            }
            if (l == 0) {
                float mu  = sum * (1.0f / HDIM);
                float var = ss  * (1.0f / HDIM) - mu * mu;
                muH[w] = mu;
                rsH[w] = rsqrtf(var + LN_EPS);
            }
        }
        nbar_sync(hb, 256);

        // ---- rebuild s (group 0, from registers) ----
        if (group == 0) {
            float nv0[8], nv1[8];
            if (t + 1 < T) {
                #pragma unroll
                for (int i = 0; i < 8; i++) {
                    int d = (int)xi[(m0g + i) * T + t + 1];
                    float2 tv = *(const float2*)(tab + d * HDIM + j0);
                    float sc = rsH[i];
                    float mu = muH[i];
                    nv0[i] = (hv[0][i] - mu) * sc * gm.x + bt.x + tv.x;
                    nv1[i] = (hv[1][i] - mu) * sc * gm.y + bt.y + tv.y;
                }
            } else {
                #pragma unroll
                for (int i = 0; i < 8; i++) {
                    float sc = rsH[i];
                    float mu = muH[i];
                    nv0[i] = (hv[0][i] - mu) * sc * gm.x + bt.x;
                    nv1[i] = (hv[1][i] - mu) * sc * gm.y + bt.y;
                }
            }
            *(float4*)(sH + j0 * SPAD)           = make_float4(nv0[0], nv0[1], nv0[2], nv0[3]);
            *(float4*)(sH + j0 * SPAD + 4)       = make_float4(nv0[4], nv0[5], nv0[6], nv0[7]);
            *(float4*)(sH + (j0 + 1) * SPAD)     = make_float4(nv1[0], nv1[1], nv1[2], nv1[3]);
            *(float4*)(sH + (j0 + 1) * SPAD + 4) = make_float4(nv1[4], nv1[5], nv1[6], nv1[7]);
        }
        nbar_sync(hb, 256);                              // s' visible before next step
    }

    // ---- output head: out[b0+m0g+m][c] = h_final[m] . W_out[:,c] + b_out[c] ----
    if (ht < HR * 10) {
        int m = ht / 10;
        int c = ht - m * 10;
        float a = b_out[c];
        #pragma unroll 8
        for (int k = 0; k < HDIM; k++)
            a = fmaf(sH[k * SPAD + m], __ldg(W_out + k * 10 + c), a);
        out[(size_t)(b0 + m0g + m) * 10 + c] = a;
    }
}

extern "C" void kernel_launch(void* const* d_in, const int* in_sizes, int n_in,
                              void* d_out, int out_size)
{
    const float* x       = (const float*)d_in[0];
    const float* W_embed = (const float*)d_in[1];
    const float* b_embed = (const float*)d_in[2];
    const float* W_up    = (const float*)d_in[3];
    const float* b_up    = (const float*)d_in[4];
    const float* gamma   = (const float*)d_in[5];
    const float* beta    = (const float*)d_in[6];
    const float* W_out   = (const float*)d_in[7];
    const float* b_out   = (const float*)d_in[8];
    float* out = (float*)d_out;

    int B = out_size / 10;          // 2048
    int T = in_sizes[0] / B;        // 512

    size_t smem = (size_t)NBUF * KTILE * HDIM * 4     // W buffers   131072
                + (size_t)10 * HDIM * 4               // tab          10240
                + (size_t)2 * HDIM * SPAD * 4         // s            24576
                + (size_t)2 * HR * HPAD * 4           // hbuf         16640
                + (size_t)2 * 8 * 128 * 8             // partials     16384
                + 32 * 4                              // stats
                + (size_t)16 * T                      // xi            8192
                + 64;
    cudaFuncSetAttribute(rnn_scan_kernel,
                         cudaFuncAttributeMaxDynamicSharedMemorySize, (int)smem);
    rnn_scan_kernel<<<B / 16, TPB, smem>>>(x, W_embed, b_embed, W_up, b_up,
                                           gamma, beta, W_out, b_out, out, B, T);
}

// round 7
// speedup vs baseline: 8.7073x; 2.8939x over previous
#include <cuda_runtime.h>
#include <cuda_bf16.h>

#define HDIM   256
#define TPB    512
#define SB     264        // s row stride (bf16 elems): 528B/row -> ldmatrix conflict-free
#define HB     260        // hbuf row stride (f32)
#define LN_EPS 1e-5f

// W_update pre-packed in mma B-fragment lane order, bf16 hi/lo split.
// Index: ((kt*32 + nt)*32 + lane)*2 + reg   (kt: k-tile of 16, nt: n-tile of 8)
__device__ unsigned gBhi[16 * 32 * 32 * 2];
__device__ unsigned gBlo[16 * 32 * 32 * 2];

__device__ __forceinline__ unsigned packbf(float a, float b) {
    __nv_bfloat162 t = __floats2bfloat162_rn(a, b);    // .x = a (low 16 bits)
    return *reinterpret_cast<unsigned*>(&t);
}

// Accurate fast tanh (~1e-6 rel err); recurrence is contractive (verified R3-R6).
__device__ __forceinline__ float tanh_fast(float v) {
    float e = __expf(2.0f * v);
    return 1.0f - __fdividef(2.0f, e + 1.0f);
}

__device__ __forceinline__ unsigned smem_u32(const void* p) {
    unsigned r;
    asm("{ .reg .u64 t; cvta.to.shared.u64 t, %1; cvt.u32.u64 %0, t; }" : "=r"(r) : "l"(p));
    return r;
}

__device__ __forceinline__ void ldmatrix_x4(unsigned a[4], unsigned addr) {
    asm volatile("ldmatrix.sync.aligned.m8n8.x4.shared.b16 {%0,%1,%2,%3}, [%4];"
                 : "=r"(a[0]), "=r"(a[1]), "=r"(a[2]), "=r"(a[3]) : "r"(addr));
}

__device__ __forceinline__ void mma_bf16(float c[4], const unsigned a[4],
                                         unsigned b0, unsigned b1) {
    asm volatile("mma.sync.aligned.m16n8k16.row.col.f32.bf16.bf16.f32 "
                 "{%0,%1,%2,%3}, {%4,%5,%6,%7}, {%8,%9}, {%0,%1,%2,%3};"
                 : "+f"(c[0]), "+f"(c[1]), "+f"(c[2]), "+f"(c[3])
                 : "r"(a[0]), "r"(a[1]), "r"(a[2]), "r"(a[3]), "r"(b0), "r"(b1));
}

// ---------- prep: split W_update into bf16 hi/lo, packed in B-fragment order ----------
__global__ void prep_kernel(const float* __restrict__ W) {
    int idx = blockIdx.x * 256 + threadIdx.x;          // 0..16383
    if (idx >= 16 * 32 * 32) return;
    int kt = idx >> 10;
    int nt = (idx >> 5) & 31;
    int l  = idx & 31;
    int n  = nt * 8 + (l >> 2);
    int k0 = kt * 16 + (l & 3) * 2;

    float w00 = W[(k0 + 0) * HDIM + n], w01 = W[(k0 + 1) * HDIM + n];
    float w10 = W[(k0 + 8) * HDIM + n], w11 = W[(k0 + 9) * HDIM + n];
    float h00 = __bfloat162float(__float2bfloat16_rn(w00));
    float h01 = __bfloat162float(__float2bfloat16_rn(w01));
    float h10 = __bfloat162float(__float2bfloat16_rn(w10));
    float h11 = __bfloat162float(__float2bfloat16_rn(w11));

    int base = idx * 2;
    gBhi[base + 0] = packbf(h00, h01);
    gBhi[base + 1] = packbf(h10, h11);
    gBlo[base + 0] = packbf(w00 - h00, w01 - h01);
    gBlo[base + 1] = packbf(w10 - h10, w11 - h11);
}

// ---------- main persistent scan kernel: 1 block = 16 batch rows ----------
__global__ void __launch_bounds__(TPB, 1)
rnn_scan_kernel(const float* __restrict__ x,        // [B, T, 1]
                const float* __restrict__ W_embed,  // [1, H]
                const float* __restrict__ b_embed,  // [H]
                const float* __restrict__ b_up,     // [H]
                const float* __restrict__ gamma,    // [H]
                const float* __restrict__ beta,     // [H]
                const float* __restrict__ W_out,    // [H, 10]
                const float* __restrict__ b_out,    // [10]
                float* __restrict__ out,            // [B, 10]
                int B, int T)
{
    extern __shared__ unsigned char smem_raw[];
    float* tab  = (float*)smem_raw;                       // [10][HDIM]      10240 B
    unsigned short* sHi = (unsigned short*)(tab + 10 * HDIM);   // [16][SB] bf16   8448 B
    unsigned short* sLo = sHi + 16 * SB;                        // [16][SB] bf16   8448 B
    float* hbuf = (float*)(sLo + 16 * SB);                // [16][HB]        16640 B
    float* mu_s = hbuf + 16 * HB;                         // [16]
    float* rs_s = mu_s + 16;                              // [16]
    unsigned char* xi = (unsigned char*)(rs_s + 16);      // [16][T]

    const int tid = threadIdx.x;
    const int w   = tid >> 5;                             // warp 0..15
    const int l   = tid & 31;
    const int b0  = blockIdx.x * 16;

    // rebuild mapping: thread owns cols (2jp, 2jp+1) x rows rq*4..rq*4+3
    const int jp = tid & 127;
    const int rq = tid >> 7;
    unsigned* sHiU = (unsigned*)sHi;                      // u32 = 2 bf16 cols
    unsigned* sLoU = (unsigned*)sLo;

    // epilogue bias values for this lane's 8 C elements (4 distinct n's)
    float bu4[4];
    #pragma unroll
    for (int i = 0; i < 4; i++)                           // i = nti*2 + (rg&1)
        bu4[i] = b_up[16 * w + 8 * (i >> 1) + 2 * (l & 3) + (i & 1)];

    const float2 gm2 = *(const float2*)(gamma + 2 * jp);
    const float2 bt2 = *(const float2*)(beta  + 2 * jp);

    // ---- one-time: embed table (x is an integer digit 0..9) ----
    for (int idx = tid; idx < 10 * HDIM; idx += TPB) {
        int v  = idx / HDIM;
        int hh = idx - v * HDIM;
        tab[idx] = tanh_fast((float)v * W_embed[hh] + b_embed[hh]);
    }
    for (int idx = tid; idx < 16 * T; idx += TPB) {
        int m = idx / T;
        int t = idx - m * T;
        xi[idx] = (unsigned char)__float2int_rn(x[(size_t)(b0 + m) * T + t]);
    }
    __syncthreads();

    // ---- init s for t=0 (h0 = 0 => s = inp), bf16 split ----
    #pragma unroll
    for (int i = 0; i < 4; i++) {
        int r = rq * 4 + i;
        int d = (int)xi[r * T];
        float2 tv = *(const float2*)(tab + d * HDIM + 2 * jp);
        float h0 = __bfloat162float(__float2bfloat16_rn(tv.x));
        float h1 = __bfloat162float(__float2bfloat16_rn(tv.y));
        sHiU[r * 132 + jp] = packbf(h0, h1);
        sLoU[r * 132 + jp] = packbf(tv.x - h0, tv.y - h1);
    }
    __syncthreads();

    // ldmatrix per-lane base address into sHi/sLo (row-major bf16, stride SB)
    const int rowA  = (l & 7) + 8 * ((l >> 3) & 1);
    const int colbA = 8 * (l >> 4);
    const unsigned aHiBase = smem_u32(sHi) + (unsigned)(rowA * SB + colbA) * 2u;
    const unsigned aLoBase = smem_u32(sLo) + (unsigned)(rowA * SB + colbA) * 2u;

    // B fragment pointers for this warp's two n-tiles
    const int nt0 = 2 * w, nt1 = 2 * w + 1;
    const unsigned boff0 = (unsigned)(nt0 * 32 + l) * 2u;
    const unsigned boff1 = (unsigned)(nt1 * 32 + l) * 2u;

    for (int t = 0; t < T; t++) {
        // ---------------- GEMM: D[16x16cols] for this warp ----------------
        float c0[4] = {0.f, 0.f, 0.f, 0.f};
        float c1[4] = {0.f, 0.f, 0.f, 0.f};

        uint2 bh0 = __ldg((const uint2*)(gBhi + boff0));
        uint2 bh1 = __ldg((const uint2*)(gBhi + boff1));
        uint2 bl0 = __ldg((const uint2*)(gBlo + boff0));
        uint2 bl1 = __ldg((const uint2*)(gBlo + boff1));

        #pragma unroll
        for (int kt = 0; kt < 16; kt++) {
            uint2 nh0, nh1, nl0, nl1;
            if (kt < 15) {
                unsigned o = (unsigned)(kt + 1) * 2048u;
                nh0 = __ldg((const uint2*)(gBhi + o + boff0));
                nh1 = __ldg((const uint2*)(gBhi + o + boff1));
                nl0 = __ldg((const uint2*)(gBlo + o + boff0));
                nl1 = __ldg((const uint2*)(gBlo + o + boff1));
            }
            unsigned aH[4], aL[4];
            ldmatrix_x4(aH, aHiBase + (unsigned)kt * 32u);
            ldmatrix_x4(aL, aLoBase + (unsigned)kt * 32u);

            mma_bf16(c0, aH, bh0.x, bh0.y);    // hi·hi
            mma_bf16(c0, aH, bl0.x, bl0.y);    // hi·lo
            mma_bf16(c0, aL, bh0.x, bh0.y);    // lo·hi
            mma_bf16(c1, aH, bh1.x, bh1.y);
            mma_bf16(c1, aH, bl1.x, bl1.y);
            mma_bf16(c1, aL, bh1.x, bh1.y);

            if (kt < 15) { bh0 = nh0; bh1 = nh1; bl0 = nl0; bl1 = nl1; }
        }

        // ---- bias + tanh, scatter to row-major hbuf ----
        #pragma unroll
        for (int nti = 0; nti < 2; nti++) {
            const float* cc = nti ? c1 : c0;
            #pragma unroll
            for (int rg = 0; rg < 4; rg++) {
                int r = (l >> 2) + 8 * (rg >> 1);
                int n = 16 * w + 8 * nti + 2 * (l & 3) + (rg & 1);
                hbuf[r * HB + n] = tanh_fast(cc[rg] + bu4[nti * 2 + (rg & 1)]);
            }
        }
        __syncthreads();

        // ---- LN stats: warp w handles row w ----
        {
            const float4* row = (const float4*)(hbuf + w * HB);
            float4 v0 = row[l * 2 + 0];
            float4 v1 = row[l * 2 + 1];
            float sum = v0.x + v0.y + v0.z + v0.w + v1.x + v1.y + v1.z + v1.w;
            float ss  = v0.x * v0.x + v0.y * v0.y + v0.z * v0.z + v0.w * v0.w
                      + v1.x * v1.x + v1.y * v1.y + v1.z * v1.z + v1.w * v1.w;
            #pragma unroll
            for (int o = 16; o >= 1; o >>= 1) {
                sum += __shfl_xor_sync(0xffffffffu, sum, o);
                ss  += __shfl_xor_sync(0xffffffffu, ss,  o);
            }
            if (l == 0) {
                float mu  = sum * (1.0f / HDIM);
                float var = ss  * (1.0f / HDIM) - mu * mu;
                mu_s[w] = mu;
                rs_s[w] = rsqrtf(var + LN_EPS);
            }
        }
        __syncthreads();

        // ---- rebuild s (LN + next-step embed), bf16 split ----
        const bool last = (t + 1 >= T);
        #pragma unroll
        for (int i = 0; i < 4; i++) {
            int r = rq * 4 + i;
            float2 hv = *(const float2*)(hbuf + r * HB + 2 * jp);
            float mu = mu_s[r], rs = rs_s[r];
            float v0 = (hv.x - mu) * rs * gm2.x + bt2.x;
            float v1 = (hv.y - mu) * rs * gm2.y + bt2.y;
            if (!last) {
                int d = (int)xi[r * T + t + 1];
                float2 tv = *(const float2*)(tab + d * HDIM + 2 * jp);
                v0 += tv.x;
                v1 += tv.y;
            }
            float h0 = __bfloat162float(__float2bfloat16_rn(v0));
            float h1 = __bfloat162float(__float2bfloat16_rn(v1));
            sHiU[r * 132 + jp] = packbf(h0, h1);
            sLoU[r * 132 + jp] = packbf(v0 - h0, v1 - h1);
        }
        __syncthreads();
    }

    // ---- output head: h_final = sHi + sLo (row-major), 160 dot products ----
    if (tid < 160) {
        int m = tid / 10;
        int cx = tid - m * 10;
        const __nv_bfloat16* rh = (const __nv_bfloat16*)sHi + m * SB;
        const __nv_bfloat16* rl = (const __nv_bfloat16*)sLo + m * SB;
        float a = b_out[cx];
        #pragma unroll 8
        for (int k = 0; k < HDIM; k++) {
            float h = __bfloat162float(rh[k]) + __bfloat162float(rl[k]);
            a = fmaf(h, __ldg(W_out + k * 10 + cx), a);
        }
        out[(size_t)(b0 + m) * 10 + cx] = a;
    }
}

extern "C" void kernel_launch(void* const* d_in, const int* in_sizes, int n_in,
                              void* d_out, int out_size)
{
    const float* x       = (const float*)d_in[0];
    const float* W_embed = (const float*)d_in[1];
    const float* b_embed = (const float*)d_in[2];
    const float* W_up    = (const float*)d_in[3];
    const float* b_up    = (const float*)d_in[4];
    const float* gamma   = (const float*)d_in[5];
    const float* beta    = (const float*)d_in[6];
    const float* W_out   = (const float*)d_in[7];
    const float* b_out   = (const float*)d_in[8];
    float* out = (float*)d_out;

    int B = out_size / 10;          // 2048
    int T = in_sizes[0] / B;        // 512

    prep_kernel<<<64, 256>>>(W_up);

    size_t smem = (size_t)10 * HDIM * 4        // tab
                + (size_t)2 * 16 * SB * 2      // sHi + sLo
                + (size_t)16 * HB * 4          // hbuf
                + 32 * 4                       // stats
                + (size_t)16 * T               // xi
                + 64;
    cudaFuncSetAttribute(rnn_scan_kernel,
                         cudaFuncAttributeMaxDynamicSharedMemorySize, (int)smem);
    rnn_scan_kernel<<<B / 16, TPB, smem>>>(x, W_embed, b_embed, b_up,
                                           gamma, beta, W_out, b_out, out, B, T);
}

// round 8
// speedup vs baseline: 9.0966x; 1.0447x over previous
#include <cuda_runtime.h>
#include <cuda_bf16.h>

#define HDIM   256
#define TPB    512
#define SB     264        // s row stride (bf16)
#define TPAD   264        // tab row stride (f32) — spreads digit-indexed banks
#define XSTR   10         // xbuf lane stride (floats)
#define LN_EPS 1e-5f

// W_update pre-packed in mma B-fragment lane order, bf16 hi/lo split.
// gBhi index: ((kt*32 + nt)*32 + lane)*2 + reg
// gBlo2 index: (kt*16 + ntp)*32 + lane  -> uint4 {nt0.r0, nt0.r1, nt1.r0, nt1.r1}
__device__ unsigned gBhi[16 * 32 * 32 * 2];
__device__ uint4    gBlo2[16 * 16 * 32];

__device__ __forceinline__ unsigned packbf(float a, float b) {
    __nv_bfloat162 t = __floats2bfloat162_rn(a, b);
    return *reinterpret_cast<unsigned*>(&t);
}
__device__ __forceinline__ float bfr(float v) {          // round-trip to bf16
    return __bfloat162float(__float2bfloat16_rn(v));
}
// Accurate fast tanh (~1e-6 rel err); recurrence is contractive (verified R3-R7).
__device__ __forceinline__ float tanh_fast(float v) {
    float e = __expf(2.0f * v);
    return 1.0f - __fdividef(2.0f, e + 1.0f);
}
__device__ __forceinline__ unsigned smem_u32(const void* p) {
    unsigned r;
    asm("{ .reg .u64 t; cvta.to.shared.u64 t, %1; cvt.u32.u64 %0, t; }" : "=r"(r) : "l"(p));
    return r;
}
__device__ __forceinline__ void ldmatrix_x4(unsigned a[4], unsigned addr) {
    asm volatile("ldmatrix.sync.aligned.m8n8.x4.shared.b16 {%0,%1,%2,%3}, [%4];"
                 : "=r"(a[0]), "=r"(a[1]), "=r"(a[2]), "=r"(a[3]) : "r"(addr));
}
__device__ __forceinline__ void mma_bf16(float c[4], const unsigned a[4],
                                         unsigned b0, unsigned b1) {
    asm volatile("mma.sync.aligned.m16n8k16.row.col.f32.bf16.bf16.f32 "
                 "{%0,%1,%2,%3}, {%4,%5,%6,%7}, {%8,%9}, {%0,%1,%2,%3};"
                 : "+f"(c[0]), "+f"(c[1]), "+f"(c[2]), "+f"(c[3])
                 : "r"(a[0]), "r"(a[1]), "r"(a[2]), "r"(a[3]), "r"(b0), "r"(b1));
}

// ---------- prep: split W into bf16 hi/lo in fragment order ----------
__global__ void prep_kernel(const float* __restrict__ W) {
    int idx = blockIdx.x * 256 + threadIdx.x;            // (kt, ntp, l): 16*16*32
    if (idx >= 16 * 16 * 32) return;
    int kt  = idx >> 9;
    int ntp = (idx >> 5) & 15;
    int l   = idx & 31;

    unsigned lo[4];
    #pragma unroll
    for (int s = 0; s < 2; s++) {
        int nt = 2 * ntp + s;
        int n  = nt * 8 + (l >> 2);
        int k0 = kt * 16 + (l & 3) * 2;
        float w00 = W[(k0 + 0) * HDIM + n], w01 = W[(k0 + 1) * HDIM + n];
        float w10 = W[(k0 + 8) * HDIM + n], w11 = W[(k0 + 9) * HDIM + n];
        float h00 = bfr(w00), h01 = bfr(w01), h10 = bfr(w10), h11 = bfr(w11);
        int base = ((kt * 32 + nt) * 32 + l) * 2;
        gBhi[base + 0] = packbf(h00, h01);
        gBhi[base + 1] = packbf(h10, h11);
        lo[s * 2 + 0] = packbf(w00 - h00, w01 - h01);
        lo[s * 2 + 1] = packbf(w10 - h10, w11 - h11);
    }
    gBlo2[(kt * 16 + ntp) * 32 + l] = make_uint4(lo[0], lo[1], lo[2], lo[3]);
}

// ---------- main persistent scan: 1 block = 16 batch rows ----------
__global__ void __launch_bounds__(TPB, 1)
rnn_scan_kernel(const float* __restrict__ x,        // [B, T, 1]
                const float* __restrict__ W_embed,  // [1, H]
                const float* __restrict__ b_embed,  // [H]
                const float* __restrict__ b_up,     // [H]
                const float* __restrict__ gamma,    // [H]
                const float* __restrict__ beta,     // [H]
                const float* __restrict__ W_out,    // [H, 10]
                const float* __restrict__ b_out,    // [10]
                float* __restrict__ out,            // [B, 10]
                int B, int T)
{
    extern __shared__ unsigned char smem_raw[];
    float* tabS = (float*)smem_raw;                       // [10][TPAD]     10560 B
    float* bS   = tabS + 10 * TPAD;                       // [256]
    float* gS   = bS + 256;
    float* btS  = gS + 256;                               //                 3072 B
    float* xbuf = btS + 256;                              // [2][8][32][XSTR] 20480 B
    float* pSum = xbuf + 2 * 8 * 32 * XSTR;               // [16][8]
    float* pSq  = pSum + 128;                             //                 1024 B
    unsigned short* sHi = (unsigned short*)(pSq + 128);   // [16][SB]        8448 B
    unsigned short* sLo = sHi + 16 * SB;                  //                 8448 B
    unsigned char*  xiT = (unsigned char*)(sLo + 16 * SB);// [T][16]         8192 B

    const int tid = threadIdx.x;
    const int w   = tid >> 5;
    const int l   = tid & 31;
    const int wc  = w & 7;                                // col group: cols [32wc, 32wc+32)
    const int kh  = w >> 3;                               // k half: kt in [8kh, 8kh+8)
    const int b0  = blockIdx.x * 16;

    unsigned* sHiU = (unsigned*)sHi;
    unsigned* sLoU = (unsigned*)sLo;

    // ---- persistent B-hi fragments: 4 n-tiles x 8 k-tiles x uint2 = 64 regs ----
    unsigned bh[4][8][2];
    #pragma unroll
    for (int nti = 0; nti < 4; nti++)
        #pragma unroll
        for (int kk = 0; kk < 8; kk++) {
            int kt = kh * 8 + kk;
            uint2 v = __ldg((const uint2*)(gBhi + ((kt * 32 + 4 * wc + nti) * 32 + l) * 2));
            bh[nti][kk][0] = v.x; bh[nti][kk][1] = v.y;
        }
    const uint4* loP0 = gBlo2 + ((kh * 8) * 16 + 2 * wc) * 32 + l;
    const uint4* loP1 = loP0 + 32;                        // ntp+1

    // ---- one-time tables ----
    for (int idx = tid; idx < 10 * HDIM; idx += TPB) {
        int v  = idx / HDIM;
        int hh = idx - v * HDIM;
        tabS[v * TPAD + hh] = tanh_fast((float)v * W_embed[hh] + b_embed[hh]);
    }
    for (int idx = tid; idx < HDIM; idx += TPB) {
        bS[idx]  = b_up[idx];
        gS[idx]  = gamma[idx];
        btS[idx] = beta[idx];
    }
    for (int idx = tid; idx < 16 * T; idx += TPB) {
        int t = idx >> 4, m = idx & 15;
        xiT[t * 16 + m] = (unsigned char)__float2int_rn(x[(size_t)(b0 + m) * T + t]);
    }
    __syncthreads();

    // this lane's row (after exchange) and base column
    const int rr = (l >> 2) + kh * 8;

    // ---- init s for t=0 (h0 = 0 => s = inp) ----
    {
        int dd = (int)xiT[rr];
        #pragma unroll
        for (int nti = 0; nti < 4; nti++) {
            int c0 = 32 * wc + 8 * nti + 2 * (l & 3);
            float2 tv = *(const float2*)(tabS + dd * TPAD + c0);
            float h0 = bfr(tv.x), h1 = bfr(tv.y);
            sHiU[rr * 132 + (c0 >> 1)] = packbf(h0, h1);
            sLoU[rr * 132 + (c0 >> 1)] = packbf(tv.x - h0, tv.y - h1);
        }
    }
    __syncthreads();

    // ldmatrix per-lane base (A frag, row-major bf16 stride SB)
    const int rowA  = (l & 7) + 8 * ((l >> 3) & 1);
    const int colbA = 8 * (l >> 4);
    const unsigned aHiBase = smem_u32(sHi) + (unsigned)(rowA * SB + colbA) * 2u
                           + (unsigned)(kh * 8) * 32u;
    const unsigned aLoBase = smem_u32(sLo) + (unsigned)(rowA * SB + colbA) * 2u
                           + (unsigned)(kh * 8) * 32u;

    float* xA = xbuf;                                     // kh1 -> kh0 (rows 0-7)
    float* xB = xbuf + 8 * 32 * XSTR;                     // kh0 -> kh1 (rows 8-15)
    float* xMineW = (kh ? xA : xB) + (wc * 32 + l) * XSTR;
    float* xMineR = (kh ? xB : xA) + (wc * 32 + l) * XSTR;

    for (int t = 0; t < T; t++) {
        // ---------------- GEMM: partial C over this warp's k-half ----------------
        float acc[4][4];
        #pragma unroll
        for (int i = 0; i < 4; i++)
            #pragma unroll
            for (int p = 0; p < 4; p++) acc[i][p] = 0.f;

        uint4 lo0 = __ldg(loP0), lo1 = __ldg(loP1);
        #pragma unroll
        for (int kk = 0; kk < 8; kk++) {
            unsigned aH[4], aL[4];
            ldmatrix_x4(aH, aHiBase + (unsigned)kk * 32u);
            ldmatrix_x4(aL, aLoBase + (unsigned)kk * 32u);
            uint4 n0, n1;
            if (kk < 7) { n0 = __ldg(loP0 + (kk + 1) * 512); n1 = __ldg(loP1 + (kk + 1) * 512); }

            mma_bf16(acc[0], aH, bh[0][kk][0], bh[0][kk][1]);   // hi*hi
            mma_bf16(acc[1], aH, bh[1][kk][0], bh[1][kk][1]);
            mma_bf16(acc[2], aH, bh[2][kk][0], bh[2][kk][1]);
            mma_bf16(acc[3], aH, bh[3][kk][0], bh[3][kk][1]);
            mma_bf16(acc[0], aL, bh[0][kk][0], bh[0][kk][1]);   // lo*hi
            mma_bf16(acc[1], aL, bh[1][kk][0], bh[1][kk][1]);
            mma_bf16(acc[2], aL, bh[2][kk][0], bh[2][kk][1]);
            mma_bf16(acc[3], aL, bh[3][kk][0], bh[3][kk][1]);
            mma_bf16(acc[0], aH, lo0.x, lo0.y);                 // hi*lo
            mma_bf16(acc[1], aH, lo0.z, lo0.w);
            mma_bf16(acc[2], aH, lo1.x, lo1.y);
            mma_bf16(acc[3], aH, lo1.z, lo1.w);
            if (kk < 7) { lo0 = n0; lo1 = n1; }
        }

        // ---- row-split K exchange: kh0 keeps rows 0-7, kh1 rows 8-15 ----
        #pragma unroll
        for (int nti = 0; nti < 4; nti++) {
            float2 snd = kh ? make_float2(acc[nti][0], acc[nti][1])
                            : make_float2(acc[nti][2], acc[nti][3]);
            *(float2*)(xMineW + nti * 2) = snd;
        }
        __syncthreads();

        float hv[4][2];
        #pragma unroll
        for (int nti = 0; nti < 4; nti++) {
            float2 o = *(const float2*)(xMineR + nti * 2);
            float v0 = (kh ? acc[nti][2] : acc[nti][0]) + o.x;
            float v1 = (kh ? acc[nti][3] : acc[nti][1]) + o.y;
            float2 bb = *(const float2*)(bS + 32 * wc + 8 * nti + 2 * (l & 3));
            hv[nti][0] = tanh_fast(v0 + bb.x);
            hv[nti][1] = tanh_fast(v1 + bb.y);
        }

        // ---- LN partials: reduce this lane's 8 cols, then over l&3 ----
        {
            float sum = 0.f, sq = 0.f;
            #pragma unroll
            for (int nti = 0; nti < 4; nti++) {
                sum += hv[nti][0] + hv[nti][1];
                sq  += hv[nti][0] * hv[nti][0] + hv[nti][1] * hv[nti][1];
            }
            sum += __shfl_xor_sync(0xffffffffu, sum, 1);
            sum += __shfl_xor_sync(0xffffffffu, sum, 2);
            sq  += __shfl_xor_sync(0xffffffffu, sq, 1);
            sq  += __shfl_xor_sync(0xffffffffu, sq, 2);
            if ((l & 3) == 0) { pSum[rr * 8 + wc] = sum; pSq[rr * 8 + wc] = sq; }
        }
        __syncthreads();

        // ---- stats finalize (redundant per warp for its 8 rows) + shfl distribute ----
        float mu = 0.f, rs = 0.f;
        if (l < 8) {
            int r8 = kh * 8 + l;
            float4 s0 = *(const float4*)(pSum + r8 * 8);
            float4 s1 = *(const float4*)(pSum + r8 * 8 + 4);
            float4 q0 = *(const float4*)(pSq  + r8 * 8);
            float4 q1 = *(const float4*)(pSq  + r8 * 8 + 4);
            float sm = s0.x + s0.y + s0.z + s0.w + s1.x + s1.y + s1.z + s1.w;
            float qq = q0.x + q0.y + q0.z + q0.w + q1.x + q1.y + q1.z + q1.w;
            mu = sm * (1.0f / HDIM);
            rs = rsqrtf(qq * (1.0f / HDIM) - mu * mu + LN_EPS);
        }
        mu = __shfl_sync(0xffffffffu, mu, l >> 2);
        rs = __shfl_sync(0xffffffffu, rs, l >> 2);

        // ---- rebuild s for this lane's (row, 8 cols) ----
        const bool last = (t + 1 >= T);
        int dd = last ? 0 : (int)xiT[(t + 1) * 16 + rr];
        #pragma unroll
        for (int nti = 0; nti < 4; nti++) {
            int c0 = 32 * wc + 8 * nti + 2 * (l & 3);
            float2 gg = *(const float2*)(gS  + c0);
            float2 bb = *(const float2*)(btS + c0);
            float v0 = (hv[nti][0] - mu) * rs * gg.x + bb.x;
            float v1 = (hv[nti][1] - mu) * rs * gg.y + bb.y;
            if (!last) {
                float2 tv = *(const float2*)(tabS + dd * TPAD + c0);
                v0 += tv.x; v1 += tv.y;
            }
            float h0 = bfr(v0), h1 = bfr(v1);
            sHiU[rr * 132 + (c0 >> 1)] = packbf(h0, h1);
            sLoU[rr * 132 + (c0 >> 1)] = packbf(v0 - h0, v1 - h1);
        }
        __syncthreads();
    }

    // ---- output head: h_final = sHi + sLo ----
    if (tid < 160) {
        int m  = tid / 10;
        int cx = tid - m * 10;
        const __nv_bfloat16* rh = (const __nv_bfloat16*)sHi + m * SB;
        const __nv_bfloat16* rl = (const __nv_bfloat16*)sLo + m * SB;
        float a = b_out[cx];
        #pragma unroll 8
        for (int k = 0; k < HDIM; k++) {
            float h = __bfloat162float(rh[k]) + __bfloat162float(rl[k]);
            a = fmaf(h, __ldg(W_out + k * 10 + cx), a);
        }
        out[(size_t)(b0 + m) * 10 + cx] = a;
    }
}

extern "C" void kernel_launch(void* const* d_in, const int* in_sizes, int n_in,
                              void* d_out, int out_size)
{
    const float* x       = (const float*)d_in[0];
    const float* W_embed = (const float*)d_in[1];
    const float* b_embed = (const float*)d_in[2];
    const float* W_up    = (const float*)d_in[3];
    const float* b_up    = (const float*)d_in[4];
    const float* gamma   = (const float*)d_in[5];
    const float* beta    = (const float*)d_in[6];
    const float* W_out   = (const float*)d_in[7];
    const float* b_out   = (const float*)d_in[8];
    float* out = (float*)d_out;

    int B = out_size / 10;          // 2048
    int T = in_sizes[0] / B;        // 512

    prep_kernel<<<32, 256>>>(W_up);

    size_t smem = (size_t)10 * TPAD * 4          // tabS       10560
                + 3 * 256 * 4                    // bias/gamma/beta
                + (size_t)2 * 8 * 32 * XSTR * 4  // xbuf       20480
                + 2 * 128 * 4                    // pSum/pSq
                + (size_t)2 * 16 * SB * 2        // sHi/sLo    16896
                + (size_t)16 * T                 // xiT         8192
                + 64;
    cudaFuncSetAttribute(rnn_scan_kernel,
                         cudaFuncAttributeMaxDynamicSharedMemorySize, (int)smem);
    rnn_scan_kernel<<<B / 16, TPB, smem>>>(x, W_embed, b_embed, b_up,
                                           gamma, beta, W_out, b_out, out, B, T);
}

// round 9
// speedup vs baseline: 9.3120x; 1.0237x over previous
#include <cuda_runtime.h>
#include <cuda_bf16.h>

#define HDIM   256
#define TPB    512
#define SB     264        // s row stride (bf16)
#define TPAD   264        // tab row stride (f32)
#define XSTR   10         // xbuf lane stride (floats)
#define LN_EPS 1e-5f

// W_update pre-packed in mma B-fragment lane order, bf16 hi/lo split, uint4-packed:
// index (kt*16 + ntp)*32 + lane -> {nt0.r0, nt0.r1, nt1.r0, nt1.r1},  nt = 2*ntp + s
__device__ uint4 gBhi2[16 * 16 * 32];
__device__ uint4 gBlo2[16 * 16 * 32];

__device__ __forceinline__ unsigned packbf(float a, float b) {
    __nv_bfloat162 t = __floats2bfloat162_rn(a, b);
    return *reinterpret_cast<unsigned*>(&t);
}
__device__ __forceinline__ float bfr(float v) {
    return __bfloat162float(__float2bfloat16_rn(v));
}
// Accurate fast tanh (~1e-6 rel err); recurrence is contractive (verified R3-R8).
__device__ __forceinline__ float tanh_fast(float v) {
    float e = __expf(2.0f * v);
    return 1.0f - __fdividef(2.0f, e + 1.0f);
}
__device__ __forceinline__ unsigned smem_u32(const void* p) {
    unsigned r;
    asm("{ .reg .u64 t; cvta.to.shared.u64 t, %1; cvt.u32.u64 %0, t; }" : "=r"(r) : "l"(p));
    return r;
}
__device__ __forceinline__ void ldmatrix_x4(unsigned a[4], unsigned addr) {
    asm volatile("ldmatrix.sync.aligned.m8n8.x4.shared.b16 {%0,%1,%2,%3}, [%4];"
                 : "=r"(a[0]), "=r"(a[1]), "=r"(a[2]), "=r"(a[3]) : "r"(addr));
}
__device__ __forceinline__ void mma_bf16(float c[4], const unsigned a[4],
                                         unsigned b0, unsigned b1) {
    asm volatile("mma.sync.aligned.m16n8k16.row.col.f32.bf16.bf16.f32 "
                 "{%0,%1,%2,%3}, {%4,%5,%6,%7}, {%8,%9}, {%0,%1,%2,%3};"
                 : "+f"(c[0]), "+f"(c[1]), "+f"(c[2]), "+f"(c[3])
                 : "r"(a[0]), "r"(a[1]), "r"(a[2]), "r"(a[3]), "r"(b0), "r"(b1));
}

// ---------- prep: split W into bf16 hi/lo in uint4 fragment order ----------
__global__ void prep_kernel(const float* __restrict__ W) {
    int idx = blockIdx.x * 256 + threadIdx.x;            // (kt, ntp, l): 16*16*32
    if (idx >= 16 * 16 * 32) return;
    int kt  = idx >> 9;
    int ntp = (idx >> 5) & 15;
    int l   = idx & 31;

    unsigned hi[4], lo[4];
    #pragma unroll
    for (int s = 0; s < 2; s++) {
        int nt = 2 * ntp + s;
        int n  = nt * 8 + (l >> 2);
        int k0 = kt * 16 + (l & 3) * 2;
        float w00 = W[(k0 + 0) * HDIM + n], w01 = W[(k0 + 1) * HDIM + n];
        float w10 = W[(k0 + 8) * HDIM + n], w11 = W[(k0 + 9) * HDIM + n];
        float h00 = bfr(w00), h01 = bfr(w01), h10 = bfr(w10), h11 = bfr(w11);
        hi[s * 2 + 0] = packbf(h00, h01);
        hi[s * 2 + 1] = packbf(h10, h11);
        lo[s * 2 + 0] = packbf(w00 - h00, w01 - h01);
        lo[s * 2 + 1] = packbf(w10 - h10, w11 - h11);
    }
    gBhi2[(kt * 16 + ntp) * 32 + l] = make_uint4(hi[0], hi[1], hi[2], hi[3]);
    gBlo2[(kt * 16 + ntp) * 32 + l] = make_uint4(lo[0], lo[1], lo[2], lo[3]);
}

// ---------- main persistent scan: 1 block = 16 batch rows ----------
__global__ void __launch_bounds__(TPB, 1)
rnn_scan_kernel(const float* __restrict__ x,        // [B, T, 1]
                const float* __restrict__ W_embed,  // [1, H]
                const float* __restrict__ b_embed,  // [H]
                const float* __restrict__ b_up,     // [H]
                const float* __restrict__ gamma,    // [H]
                const float* __restrict__ beta,     // [H]
                const float* __restrict__ W_out,    // [H, 10]
                const float* __restrict__ b_out,    // [10]
                float* __restrict__ out,            // [B, 10]
                int B, int T)
{
    extern __shared__ unsigned char smem_raw[];
    float* tabS = (float*)smem_raw;                       // [10][TPAD]
    float* bS   = tabS + 10 * TPAD;                       // [256]
    float* gS   = bS + 256;
    float* btS  = gS + 256;
    float* xbuf = btS + 256;                              // [2][8][32][XSTR]
    float* pSum = xbuf + 2 * 8 * 32 * XSTR;               // [16][8]
    float* pSq  = pSum + 128;
    unsigned short* sHi = (unsigned short*)(pSq + 128);   // [16][SB]
    unsigned short* sLo = sHi + 16 * SB;
    unsigned char*  xiT = (unsigned char*)(sLo + 16 * SB);// [T][16]

    const int tid = threadIdx.x;
    const int w   = tid >> 5;
    const int l   = tid & 31;
    const int wc  = w & 7;                                // cols [32wc, 32wc+32)
    const int kh  = w >> 3;                               // k half
    const int b0  = blockIdx.x * 16;

    unsigned* sHiU = (unsigned*)sHi;
    unsigned* sLoU = (unsigned*)sLo;

    // B fragment stream pointers (per-step LDG.128, L1-resident)
    const uint4* hiP0 = gBhi2 + ((kh * 8) * 16 + 2 * wc) * 32 + l;
    const uint4* hiP1 = hiP0 + 32;
    const uint4* loP0 = gBlo2 + ((kh * 8) * 16 + 2 * wc) * 32 + l;
    const uint4* loP1 = loP0 + 32;

    // ---- one-time tables ----
    for (int idx = tid; idx < 10 * HDIM; idx += TPB) {
        int v  = idx / HDIM;
        int hh = idx - v * HDIM;
        tabS[v * TPAD + hh] = tanh_fast((float)v * W_embed[hh] + b_embed[hh]);
    }
    for (int idx = tid; idx < HDIM; idx += TPB) {
        bS[idx]  = b_up[idx];
        gS[idx]  = gamma[idx];
        btS[idx] = beta[idx];
    }
    for (int idx = tid; idx < 16 * T; idx += TPB) {
        int t = idx >> 4, m = idx & 15;
        xiT[t * 16 + m] = (unsigned char)__float2int_rn(x[(size_t)(b0 + m) * T + t]);
    }
    __syncthreads();

    const int rr = (l >> 2) + kh * 8;                     // lane's row after exchange

    // ---- init s for t=0 (h0 = 0 => s = inp) ----
    {
        int dd = (int)xiT[rr];
        #pragma unroll
        for (int nti = 0; nti < 4; nti++) {
            int c0 = 32 * wc + 8 * nti + 2 * (l & 3);
            float2 tv = *(const float2*)(tabS + dd * TPAD + c0);
            float h0 = bfr(tv.x), h1 = bfr(tv.y);
            sHiU[rr * 132 + (c0 >> 1)] = packbf(h0, h1);
            sLoU[rr * 132 + (c0 >> 1)] = packbf(tv.x - h0, tv.y - h1);
        }
    }
    __syncthreads();

    // ldmatrix per-lane base (A frag, row-major bf16 stride SB)
    const int rowA  = (l & 7) + 8 * ((l >> 3) & 1);
    const int colbA = 8 * (l >> 4);
    const unsigned aHiBase = smem_u32(sHi) + (unsigned)(rowA * SB + colbA) * 2u
                           + (unsigned)(kh * 8) * 32u;
    const unsigned aLoBase = smem_u32(sLo) + (unsigned)(rowA * SB + colbA) * 2u
                           + (unsigned)(kh * 8) * 32u;

    float* xA = xbuf;                                     // kh1 -> kh0 (rows 0-7)
    float* xB = xbuf + 8 * 32 * XSTR;                     // kh0 -> kh1 (rows 8-15)
    float* xMineW = (kh ? xA : xB) + (wc * 32 + l) * XSTR;
    float* xMineR = (kh ? xB : xA) + (wc * 32 + l) * XSTR;

    for (int t = 0; t < T; t++) {
        // ---------------- GEMM: partial C over this warp's k-half ----------------
        float acc[4][4];
        #pragma unroll
        for (int i = 0; i < 4; i++)
            #pragma unroll
            for (int p = 0; p < 4; p++) acc[i][p] = 0.f;

        // 2-slot software pipeline: B (LDG.128 x4) + A (ldmatrix.x4 x2)
        uint4 h0[2], h1[2], lo0[2], lo1[2];
        unsigned aH[2][4], aL[2][4];

        h0[0]  = __ldg(hiP0);
        h1[0]  = __ldg(hiP1);
        lo0[0] = __ldg(loP0);
        lo1[0] = __ldg(loP1);
        ldmatrix_x4(aH[0], aHiBase);
        ldmatrix_x4(aL[0], aLoBase);

        #pragma unroll
        for (int kk = 0; kk < 8; kk++) {
            const int cur = kk & 1, nxt = cur ^ 1;
            if (kk < 7) {
                h0[nxt]  = __ldg(hiP0 + (kk + 1) * 512);
                h1[nxt]  = __ldg(hiP1 + (kk + 1) * 512);
                lo0[nxt] = __ldg(loP0 + (kk + 1) * 512);
                lo1[nxt] = __ldg(loP1 + (kk + 1) * 512);
                ldmatrix_x4(aH[nxt], aHiBase + (unsigned)(kk + 1) * 32u);
                ldmatrix_x4(aL[nxt], aLoBase + (unsigned)(kk + 1) * 32u);
            }
            mma_bf16(acc[0], aH[cur], h0[cur].x, h0[cur].y);    // hi*hi
            mma_bf16(acc[1], aH[cur], h0[cur].z, h0[cur].w);
            mma_bf16(acc[2], aH[cur], h1[cur].x, h1[cur].y);
            mma_bf16(acc[3], aH[cur], h1[cur].z, h1[cur].w);
            mma_bf16(acc[0], aL[cur], h0[cur].x, h0[cur].y);    // lo*hi
            mma_bf16(acc[1], aL[cur], h0[cur].z, h0[cur].w);
            mma_bf16(acc[2], aL[cur], h1[cur].x, h1[cur].y);
            mma_bf16(acc[3], aL[cur], h1[cur].z, h1[cur].w);
            mma_bf16(acc[0], aH[cur], lo0[cur].x, lo0[cur].y);  // hi*lo
            mma_bf16(acc[1], aH[cur], lo0[cur].z, lo0[cur].w);
            mma_bf16(acc[2], aH[cur], lo1[cur].x, lo1[cur].y);
            mma_bf16(acc[3], aH[cur], lo1[cur].z, lo1[cur].w);
        }

        // ---- row-split K exchange: kh0 keeps rows 0-7, kh1 rows 8-15 ----
        #pragma unroll
        for (int nti = 0; nti < 4; nti++) {
            float2 snd = kh ? make_float2(acc[nti][0], acc[nti][1])
                            : make_float2(acc[nti][2], acc[nti][3]);
            *(float2*)(xMineW + nti * 2) = snd;
        }
        __syncthreads();

        float hv[4][2];
        #pragma unroll
        for (int nti = 0; nti < 4; nti++) {
            float2 o = *(const float2*)(xMineR + nti * 2);
            float v0 = (kh ? acc[nti][2] : acc[nti][0]) + o.x;
            float v1 = (kh ? acc[nti][3] : acc[nti][1]) + o.y;
            float2 bb = *(const float2*)(bS + 32 * wc + 8 * nti + 2 * (l & 3));
            hv[nti][0] = tanh_fast(v0 + bb.x);
            hv[nti][1] = tanh_fast(v1 + bb.y);
        }

        // ---- LN partials: reduce lane's 8 cols, then over quad ----
        {
            float sum = 0.f, sq = 0.f;
            #pragma unroll
            for (int nti = 0; nti < 4; nti++) {
                sum += hv[nti][0] + hv[nti][1];
                sq  += hv[nti][0] * hv[nti][0] + hv[nti][1] * hv[nti][1];
            }
            sum += __shfl_xor_sync(0xffffffffu, sum, 1);
            sum += __shfl_xor_sync(0xffffffffu, sum, 2);
            sq  += __shfl_xor_sync(0xffffffffu, sq, 1);
            sq  += __shfl_xor_sync(0xffffffffu, sq, 2);
            if ((l & 3) == 0) { pSum[rr * 8 + wc] = sum; pSq[rr * 8 + wc] = sq; }
        }
        __syncthreads();

        // ---- stats finalize + shfl distribute ----
        float mu = 0.f, rs = 0.f;
        if (l < 8) {
            int r8 = kh * 8 + l;
            float4 s0 = *(const float4*)(pSum + r8 * 8);
            float4 s1 = *(const float4*)(pSum + r8 * 8 + 4);
            float4 q0 = *(const float4*)(pSq  + r8 * 8);
            float4 q1 = *(const float4*)(pSq  + r8 * 8 + 4);
            float sm = s0.x + s0.y + s0.z + s0.w + s1.x + s1.y + s1.z + s1.w;
            float qq = q0.x + q0.y + q0.z + q0.w + q1.x + q1.y + q1.z + q1.w;
            mu = sm * (1.0f / HDIM);
            rs = rsqrtf(qq * (1.0f / HDIM) - mu * mu + LN_EPS);
        }
        mu = __shfl_sync(0xffffffffu, mu, l >> 2);
        rs = __shfl_sync(0xffffffffu, rs, l >> 2);

        // ---- rebuild s for this lane's (row, 8 cols) ----
        const bool last = (t + 1 >= T);
        int dd = last ? 0 : (int)xiT[(t + 1) * 16 + rr];
        #pragma unroll
        for (int nti = 0; nti < 4; nti++) {
            int c0 = 32 * wc + 8 * nti + 2 * (l & 3);
            float2 gg = *(const float2*)(gS  + c0);
            float2 bb = *(const float2*)(btS + c0);
            float v0 = (hv[nti][0] - mu) * rs * gg.x + bb.x;
            float v1 = (hv[nti][1] - mu) * rs * gg.y + bb.y;
            if (!last) {
                float2 tv = *(const float2*)(tabS + dd * TPAD + c0);
                v0 += tv.x; v1 += tv.y;
            }
            float h0v = bfr(v0), h1v = bfr(v1);
            sHiU[rr * 132 + (c0 >> 1)] = packbf(h0v, h1v);
            sLoU[rr * 132 + (c0 >> 1)] = packbf(v0 - h0v, v1 - h1v);
        }
        __syncthreads();
    }

    // ---- output head: h_final = sHi + sLo ----
    if (tid < 160) {
        int m  = tid / 10;
        int cx = tid - m * 10;
        const __nv_bfloat16* rh = (const __nv_bfloat16*)sHi + m * SB;
        const __nv_bfloat16* rl = (const __nv_bfloat16*)sLo + m * SB;
        float a = b_out[cx];
        #pragma unroll 8
        for (int k = 0; k < HDIM; k++) {
            float h = __bfloat162float(rh[k]) + __bfloat162float(rl[k]);
            a = fmaf(h, __ldg(W_out + k * 10 + cx), a);
        }
        out[(size_t)(b0 + m) * 10 + cx] = a;
    }
}

extern "C" void kernel_launch(void* const* d_in, const int* in_sizes, int n_in,
                              void* d_out, int out_size)
{
    const float* x       = (const float*)d_in[0];
    const float* W_embed = (const float*)d_in[1];
    const float* b_embed = (const float*)d_in[2];
    const float* W_up    = (const float*)d_in[3];
    const float* b_up    = (const float*)d_in[4];
    const float* gamma   = (const float*)d_in[5];
    const float* beta    = (const float*)d_in[6];
    const float* W_out   = (const float*)d_in[7];
    const float* b_out   = (const float*)d_in[8];
    float* out = (float*)d_out;

    int B = out_size / 10;          // 2048
    int T = in_sizes[0] / B;        // 512

    prep_kernel<<<32, 256>>>(W_up);

    size_t smem = (size_t)10 * TPAD * 4
                + 3 * 256 * 4
                + (size_t)2 * 8 * 32 * XSTR * 4
                + 2 * 128 * 4
                + (size_t)2 * 16 * SB * 2
                + (size_t)16 * T
                + 64;
    cudaFuncSetAttribute(rnn_scan_kernel,
                         cudaFuncAttributeMaxDynamicSharedMemorySize, (int)smem);
    rnn_scan_kernel<<<B / 16, TPB, smem>>>(x, W_embed, b_embed, b_up,
                                           gamma, beta, W_out, b_out, out, B, T);
}

// round 10
// speedup vs baseline: 14.2964x; 1.5353x over previous
#include <cuda_runtime.h>
#include <cuda_fp16.h>

#define HDIM   256
#define TPB    512
#define SB     264        // s row stride (fp16 elems)
#define TPAD   264        // tab row stride (f32)
#define XSTR   10         // xbuf lane stride (floats)
#define LN_EPS 1e-5f

// W_update pre-packed in mma B-fragment lane order, single fp16, uint4-packed:
// index (kt*16 + ntp)*32 + lane -> {nt0.r0, nt0.r1, nt1.r0, nt1.r1},  nt = 2*ntp + s
__device__ uint4 gBh[16 * 16 * 32];

__device__ __forceinline__ unsigned packh(float a, float b) {
    __half2 t = __floats2half2_rn(a, b);
    return *reinterpret_cast<unsigned*>(&t);
}
__device__ __forceinline__ float hfr(float v) {          // round-trip to fp16
    return __half2float(__float2half_rn(v));
}
// Accurate fast tanh (~1e-6 rel err); recurrence is contractive (verified R3-R9).
__device__ __forceinline__ float tanh_fast(float v) {
    float e = __expf(2.0f * v);
    return 1.0f - __fdividef(2.0f, e + 1.0f);
}
__device__ __forceinline__ unsigned smem_u32(const void* p) {
    unsigned r;
    asm("{ .reg .u64 t; cvta.to.shared.u64 t, %1; cvt.u32.u64 %0, t; }" : "=r"(r) : "l"(p));
    return r;
}
__device__ __forceinline__ void ldmatrix_x4(unsigned a[4], unsigned addr) {
    asm volatile("ldmatrix.sync.aligned.m8n8.x4.shared.b16 {%0,%1,%2,%3}, [%4];"
                 : "=r"(a[0]), "=r"(a[1]), "=r"(a[2]), "=r"(a[3]) : "r"(addr));
}
__device__ __forceinline__ void mma_f16(float c[4], const unsigned a[4],
                                        unsigned b0, unsigned b1) {
    asm volatile("mma.sync.aligned.m16n8k16.row.col.f32.f16.f16.f32 "
                 "{%0,%1,%2,%3}, {%4,%5,%6,%7}, {%8,%9}, {%0,%1,%2,%3};"
                 : "+f"(c[0]), "+f"(c[1]), "+f"(c[2]), "+f"(c[3])
                 : "r"(a[0]), "r"(a[1]), "r"(a[2]), "r"(a[3]), "r"(b0), "r"(b1));
}

// ---------- prep: W -> fp16 in uint4 fragment order ----------
__global__ void prep_kernel(const float* __restrict__ W) {
    int idx = blockIdx.x * 256 + threadIdx.x;            // (kt, ntp, l): 16*16*32
    if (idx >= 16 * 16 * 32) return;
    int kt  = idx >> 9;
    int ntp = (idx >> 5) & 15;
    int l   = idx & 31;

    unsigned hi[4];
    #pragma unroll
    for (int s = 0; s < 2; s++) {
        int nt = 2 * ntp + s;
        int n  = nt * 8 + (l >> 2);
        int k0 = kt * 16 + (l & 3) * 2;
        hi[s * 2 + 0] = packh(W[(k0 + 0) * HDIM + n], W[(k0 + 1) * HDIM + n]);
        hi[s * 2 + 1] = packh(W[(k0 + 8) * HDIM + n], W[(k0 + 9) * HDIM + n]);
    }
    gBh[(kt * 16 + ntp) * 32 + l] = make_uint4(hi[0], hi[1], hi[2], hi[3]);
}

// ---------- main persistent scan: 1 block = 16 batch rows ----------
__global__ void __launch_bounds__(TPB, 1)
rnn_scan_kernel(const float* __restrict__ x,        // [B, T, 1]
                const float* __restrict__ W_embed,  // [1, H]
                const float* __restrict__ b_embed,  // [H]
                const float* __restrict__ b_up,     // [H]
                const float* __restrict__ gamma,    // [H]
                const float* __restrict__ beta,     // [H]
                const float* __restrict__ W_out,    // [H, 10]
                const float* __restrict__ b_out,    // [10]
                float* __restrict__ out,            // [B, 10]
                int B, int T)
{
    extern __shared__ unsigned char smem_raw[];
    float* tabS = (float*)smem_raw;                       // [10][TPAD]
    float* bS   = tabS + 10 * TPAD;                       // [256]
    float* gS   = bS + 256;
    float* btS  = gS + 256;
    float* xbuf = btS + 256;                              // [2][8][32][XSTR]
    float* pSum = xbuf + 2 * 8 * 32 * XSTR;               // [16][8]
    float* pSq  = pSum + 128;
    unsigned short* sHi = (unsigned short*)(pSq + 128);   // [16][SB] fp16
    unsigned short* sLo = sHi + 16 * SB;                  // [16][SB] fp16
    unsigned char*  xiT = (unsigned char*)(sLo + 16 * SB);// [T][16]

    const int tid = threadIdx.x;
    const int w   = tid >> 5;
    const int l   = tid & 31;
    const int wc  = w & 7;                                // cols [32wc, 32wc+32)
    const int kh  = w >> 3;                               // k half
    const int b0  = blockIdx.x * 16;

    unsigned* sHiU = (unsigned*)sHi;
    unsigned* sLoU = (unsigned*)sLo;

    // B fragment stream (per-step LDG.128; 128KB/step working set -> L1-resident)
    const uint4* hiP0 = gBh + ((kh * 8) * 16 + 2 * wc) * 32 + l;
    const uint4* hiP1 = hiP0 + 32;

    // ---- one-time tables ----
    for (int idx = tid; idx < 10 * HDIM; idx += TPB) {
        int v  = idx / HDIM;
        int hh = idx - v * HDIM;
        tabS[v * TPAD + hh] = tanh_fast((float)v * W_embed[hh] + b_embed[hh]);
    }
    for (int idx = tid; idx < HDIM; idx += TPB) {
        bS[idx]  = b_up[idx];
        gS[idx]  = gamma[idx];
        btS[idx] = beta[idx];
    }
    for (int idx = tid; idx < 16 * T; idx += TPB) {
        int t = idx >> 4, m = idx & 15;
        xiT[t * 16 + m] = (unsigned char)__float2int_rn(x[(size_t)(b0 + m) * T + t]);
    }
    __syncthreads();

    const int rr = (l >> 2) + kh * 8;                     // lane's row after exchange

    // ---- init s for t=0 (h0 = 0 => s = inp), fp16 hi/lo split ----
    {
        int dd = (int)xiT[rr];
        #pragma unroll
        for (int nti = 0; nti < 4; nti++) {
            int c0 = 32 * wc + 8 * nti + 2 * (l & 3);
            float2 tv = *(const float2*)(tabS + dd * TPAD + c0);
            float h0 = hfr(tv.x), h1 = hfr(tv.y);
            sHiU[rr * 132 + (c0 >> 1)] = packh(h0, h1);
            sLoU[rr * 132 + (c0 >> 1)] = packh(tv.x - h0, tv.y - h1);
        }
    }
    __syncthreads();

    // ldmatrix per-lane base (A frag, row-major fp16 stride SB)
    const int rowA  = (l & 7) + 8 * ((l >> 3) & 1);
    const int colbA = 8 * (l >> 4);
    const unsigned aHiBase = smem_u32(sHi) + (unsigned)(rowA * SB + colbA) * 2u
                           + (unsigned)(kh * 8) * 32u;
    const unsigned aLoBase = smem_u32(sLo) + (unsigned)(rowA * SB + colbA) * 2u
                           + (unsigned)(kh * 8) * 32u;

    float* xA = xbuf;                                     // kh1 -> kh0 (rows 0-7)
    float* xB = xbuf + 8 * 32 * XSTR;                     // kh0 -> kh1 (rows 8-15)
    float* xMineW = (kh ? xA : xB) + (wc * 32 + l) * XSTR;
    float* xMineR = (kh ? xB : xA) + (wc * 32 + l) * XSTR;

    for (int t = 0; t < T; t++) {
        // ---------------- GEMM: partial C over this warp's k-half ----------------
        float acc[4][4];
        #pragma unroll
        for (int i = 0; i < 4; i++)
            #pragma unroll
            for (int p = 0; p < 4; p++) acc[i][p] = 0.f;

        // 2-slot software pipeline: B (2x LDG.128) + A (2x ldmatrix.x4)
        uint4 h0[2], h1[2];
        unsigned aH[2][4], aL[2][4];

        h0[0] = __ldg(hiP0);
        h1[0] = __ldg(hiP1);
        ldmatrix_x4(aH[0], aHiBase);
        ldmatrix_x4(aL[0], aLoBase);

        #pragma unroll
        for (int kk = 0; kk < 8; kk++) {
            const int cur = kk & 1, nxt = cur ^ 1;
            if (kk < 7) {
                h0[nxt] = __ldg(hiP0 + (kk + 1) * 512);
                h1[nxt] = __ldg(hiP1 + (kk + 1) * 512);
                ldmatrix_x4(aH[nxt], aHiBase + (unsigned)(kk + 1) * 32u);
                ldmatrix_x4(aL[nxt], aLoBase + (unsigned)(kk + 1) * 32u);
            }
            mma_f16(acc[0], aH[cur], h0[cur].x, h0[cur].y);   // s_hi * W
            mma_f16(acc[1], aH[cur], h0[cur].z, h0[cur].w);
            mma_f16(acc[2], aH[cur], h1[cur].x, h1[cur].y);
            mma_f16(acc[3], aH[cur], h1[cur].z, h1[cur].w);
            mma_f16(acc[0], aL[cur], h0[cur].x, h0[cur].y);   // s_lo * W
            mma_f16(acc[1], aL[cur], h0[cur].z, h0[cur].w);
            mma_f16(acc[2], aL[cur], h1[cur].x, h1[cur].y);
            mma_f16(acc[3], aL[cur], h1[cur].z, h1[cur].w);
        }

        // ---- row-split K exchange: kh0 keeps rows 0-7, kh1 rows 8-15 ----
        #pragma unroll
        for (int nti = 0; nti < 4; nti++) {
            float2 snd = kh ? make_float2(acc[nti][0], acc[nti][1])
                            : make_float2(acc[nti][2], acc[nti][3]);
            *(float2*)(xMineW + nti * 2) = snd;
        }
        __syncthreads();

        float hv[4][2];
        #pragma unroll
        for (int nti = 0; nti < 4; nti++) {
            float2 o = *(const float2*)(xMineR + nti * 2);
            float v0 = (kh ? acc[nti][2] : acc[nti][0]) + o.x;
            float v1 = (kh ? acc[nti][3] : acc[nti][1]) + o.y;
            float2 bb = *(const float2*)(bS + 32 * wc + 8 * nti + 2 * (l & 3));
            hv[nti][0] = tanh_fast(v0 + bb.x);
            hv[nti][1] = tanh_fast(v1 + bb.y);
        }

        // ---- LN partials: reduce lane's 8 cols, then over quad ----
        {
            float sum = 0.f, sq = 0.f;
            #pragma unroll
            for (int nti = 0; nti < 4; nti++) {
                sum += hv[nti][0] + hv[nti][1];
                sq  += hv[nti][0] * hv[nti][0] + hv[nti][1] * hv[nti][1];
            }
            sum += __shfl_xor_sync(0xffffffffu, sum, 1);
            sum += __shfl_xor_sync(0xffffffffu, sum, 2);
            sq  += __shfl_xor_sync(0xffffffffu, sq, 1);
            sq  += __shfl_xor_sync(0xffffffffu, sq, 2);
            if ((l & 3) == 0) { pSum[rr * 8 + wc] = sum; pSq[rr * 8 + wc] = sq; }
        }
        __syncthreads();

        // ---- stats finalize + shfl distribute ----
        float mu = 0.f, rs = 0.f;
        if (l < 8) {
            int r8 = kh * 8 + l;
            float4 s0 = *(const float4*)(pSum + r8 * 8);
            float4 s1 = *(const float4*)(pSum + r8 * 8 + 4);
            float4 q0 = *(const float4*)(pSq  + r8 * 8);
            float4 q1 = *(const float4*)(pSq  + r8 * 8 + 4);
            float sm = s0.x + s0.y + s0.z + s0.w + s1.x + s1.y + s1.z + s1.w;
            float qq = q0.x + q0.y + q0.z + q0.w + q1.x + q1.y + q1.z + q1.w;
            mu = sm * (1.0f / HDIM);
            rs = rsqrtf(qq * (1.0f / HDIM) - mu * mu + LN_EPS);
        }
        mu = __shfl_sync(0xffffffffu, mu, l >> 2);
        rs = __shfl_sync(0xffffffffu, rs, l >> 2);

        // ---- rebuild s for this lane's (row, 8 cols), fp16 hi/lo split ----
        const bool last = (t + 1 >= T);
        int dd = last ? 0 : (int)xiT[(t + 1) * 16 + rr];
        #pragma unroll
        for (int nti = 0; nti < 4; nti++) {
            int c0 = 32 * wc + 8 * nti + 2 * (l & 3);
            float2 gg = *(const float2*)(gS  + c0);
            float2 bb = *(const float2*)(btS + c0);
            float v0 = (hv[nti][0] - mu) * rs * gg.x + bb.x;
            float v1 = (hv[nti][1] - mu) * rs * gg.y + bb.y;
            if (!last) {
                float2 tv = *(const float2*)(tabS + dd * TPAD + c0);
                v0 += tv.x; v1 += tv.y;
            }
            float h0v = hfr(v0), h1v = hfr(v1);
            sHiU[rr * 132 + (c0 >> 1)] = packh(h0v, h1v);
            sLoU[rr * 132 + (c0 >> 1)] = packh(v0 - h0v, v1 - h1v);
        }
        __syncthreads();
    }

    // ---- output head: h_final = sHi + sLo ----
    if (tid < 160) {
        int m  = tid / 10;
        int cx = tid - m * 10;
        const __half* rh = (const __half*)sHi + m * SB;
        const __half* rl = (const __half*)sLo + m * SB;
        float a = b_out[cx];
        #pragma unroll 8
        for (int k = 0; k < HDIM; k++) {
            float h = __half2float(rh[k]) + __half2float(rl[k]);
            a = fmaf(h, __ldg(W_out + k * 10 + cx), a);
        }
        out[(size_t)(b0 + m) * 10 + cx] = a;
    }
}

extern "C" void kernel_launch(void* const* d_in, const int* in_sizes, int n_in,
                              void* d_out, int out_size)
{
    const float* x       = (const float*)d_in[0];
    const float* W_embed = (const float*)d_in[1];
    const float* b_embed = (const float*)d_in[2];
    const float* W_up    = (const float*)d_in[3];
    const float* b_up    = (const float*)d_in[4];
    const float* gamma   = (const float*)d_in[5];
    const float* beta    = (const float*)d_in[6];
    const float* W_out   = (const float*)d_in[7];
    const float* b_out   = (const float*)d_in[8];
    float* out = (float*)d_out;

    int B = out_size / 10;          // 2048
    int T = in_sizes[0] / B;        // 512

    prep_kernel<<<32, 256>>>(W_up);

    size_t smem = (size_t)10 * TPAD * 4
                + 3 * 256 * 4
                + (size_t)2 * 8 * 32 * XSTR * 4
                + 2 * 128 * 4
                + (size_t)2 * 16 * SB * 2
                + (size_t)16 * T
                + 64;
    cudaFuncSetAttribute(rnn_scan_kernel,
                         cudaFuncAttributeMaxDynamicSharedMemorySize, (int)smem);
    rnn_scan_kernel<<<B / 16, TPB, smem>>>(x, W_embed, b_embed, b_up,
                                           gamma, beta, W_out, b_out, out, B, T);
}